// round 13
// baseline (speedup 1.0000x reference)
#include <cuda_runtime.h>
#include <math.h>

#define W 512
#define H 512
#define BATCH 16
#define NPIX (W*H)
#define NMAP (BATCH*NPIX)
#define EPSF 1e-4f
#define NT 512

#define NANF __int_as_float(0x7fffffff)

__device__ float g_gray[2 * NMAP];
__device__ double g_acc;

// ---- smem layout (float units) ----
// gray 58x58 s60 @0 (3480) ; sga 56x56 s56 @3480 (3136) ; go 44x44 s44 @6616 (1936)
// A @8552 (3520 floats): hs5/vs5 (2112) -> h72 44x38 s40 float2 (3520) -> h7s2 38x32 float2 (2432)
// B @12072 (5376): hm2 56x48 float2 (5376) -> h17f2 48x32 float2 (3072)
// C @17448 (4608): pm2 48x48 float2 (4608) -> m72 38x38 s40 float2 (3040)
#define OFF_GRAY 0
#define OFF_SGA  3480
#define OFF_GO   6616
#define OFF_A    8552
#define OFF_B    12072
#define OFF_C    17448
#define SMEM_FLOATS 22056
#define SMEM_BYTES (SMEM_FLOATS * 4)

// float2 indices
#define H72   (OFF_A / 2)
#define H7S2  (OFF_A / 2)
#define HM2   (OFF_B / 2)
#define H17F2 (OFF_B / 2)
#define PM2   (OFF_C / 2)
#define M72   (OFF_C / 2)

__global__ void k_zero() { g_acc = 0.0; }

__global__ void k_gray(const float* __restrict__ in, float* __restrict__ outp) {
    int i = blockIdx.x * blockDim.x + threadIdx.x;
    if (i >= NMAP / 4) return;
    int b = i / (NPIX / 4);
    int p = i - b * (NPIX / 4);
    const float4* base = (const float4*)(in + (size_t)b * 3 * NPIX);
    float4 r = base[p];
    float4 g = base[NPIX / 4 + p];
    float4 bl = base[2 * (NPIX / 4) + p];
    float4 o;
    o.x = 0.299f * r.x + 0.587f * g.x + 0.114f * bl.x;
    o.y = 0.299f * r.y + 0.587f * g.y + 0.114f * bl.y;
    o.z = 0.299f * r.z + 0.587f * g.z + 0.114f * bl.z;
    o.w = 0.299f * r.w + 0.587f * g.w + 0.114f * bl.w;
    ((float4*)outp)[i] = o;
}

template<int DIR, bool BORDER>
__device__ __forceinline__ void pipe(float* S, int X0, int Y0, int tid,
                                     int mode, float* vsave, double& acc)
{
    float2* S2 = reinterpret_cast<float2*>(S);
    float gmv[4], gnv[4];

    // ======== P1: sga (56x56) |grad|, NaN outside (border only) ========
    #pragma unroll
    for (int idx = tid; idx < 784; idx += NT) {
        int r = idx / 14, g4 = (idx - r * 14) * 4;
        const float* p = S + OFF_GRAY + r * 60 + g4;
        float4 a = *(const float4*)p;
        float n0, n1, n2, n3;
        if (DIR == 0) {
            float e = p[4];
            n0 = a.y; n1 = a.z; n2 = a.w; n3 = e;
        } else {
            float4 bb = *(const float4*)(p + 60);
            n0 = bb.x; n1 = bb.y; n2 = bb.z; n3 = bb.w;
        }
        float4 o;
        o.x = fabsf(a.x - n0); o.y = fabsf(a.y - n1);
        o.z = fabsf(a.z - n2); o.w = fabsf(a.w - n3);
        if (BORDER) {
            int gy = Y0 - 12 + r, gxb = X0 - 12 + g4;
            bool iny = (unsigned)gy < (unsigned)H;
            if (!(iny && (unsigned)(gxb + 0) < (unsigned)W)) o.x = NANF;
            if (!(iny && (unsigned)(gxb + 1) < (unsigned)W)) o.y = NANF;
            if (!(iny && (unsigned)(gxb + 2) < (unsigned)W)) o.z = NANF;
            if (!(iny && (unsigned)(gxb + 3) < (unsigned)W)) o.w = NANF;
        }
        *(float4*)(S + OFF_SGA + r * 56 + g4) = o;
    }
    __syncthreads();

    // ======== P2: hm2 (56x48 float2) + telescoped hs5/vs5 ========
    #pragma unroll
    for (int idx = tid; idx < 1200; idx += NT) {
        if (idx < 672) {
            int r = idx / 12, g4 = (idx - r * 12) * 4;
            const float* p = S + OFF_SGA + r * 56 + g4;
            float4 A = *(const float4*)p;
            float4 Bv = *(const float4*)(p + 4);
            float4 Cv = *(const float4*)(p + 8);
            float t0=A.x,t1=A.y,t2=A.z,t3=A.w,t4=Bv.x,t5=Bv.y,t6=Bv.z,t7=Bv.w,t8=Cv.x,t9=Cv.y,t10=Cv.z,t11=Cv.w;
            float cx = fmaxf(fmaxf(fmaxf(t3,t4),fmaxf(t5,t6)),fmaxf(t7,t8));
            float cn = fminf(fminf(fminf(t3,t4),fminf(t5,t6)),fminf(t7,t8));
            float ox0 = fmaxf(fmaxf(fmaxf(cx,t0),t1),t2);
            float ox1 = fmaxf(fmaxf(fmaxf(cx,t1),t2),t9);
            float ox2 = fmaxf(fmaxf(fmaxf(cx,t2),t9),t10);
            float ox3 = fmaxf(fmaxf(fmaxf(cx,t9),t10),t11);
            float on0 = fminf(fminf(fminf(cn,t0),t1),t2);
            float on1 = fminf(fminf(fminf(cn,t1),t2),t9);
            float on2 = fminf(fminf(fminf(cn,t2),t9),t10);
            float on3 = fminf(fminf(fminf(cn,t9),t10),t11);
            float4* dst = (float4*)(S2 + HM2 + r * 48 + g4);
            dst[0] = make_float4(ox0, on0, ox1, on1);
            dst[1] = make_float4(ox2, on2, ox3, on3);
        } else {
            int k = idx - 672;    // 528 items
            if (DIR == 0) {
                int r = k / 11, c4 = (k - r * 11) * 4;
                float4 o;
                if (!BORDER) {
                    const float* p = S + OFF_GRAY + (r + 4) * 60 + c4;
                    float4 A = *(const float4*)(p + 4);
                    float4 Bv = *(const float4*)(p + 8);
                    float e = p[12];
                    o = make_float4(A.x - Bv.y, A.y - Bv.z, A.z - Bv.w, A.w - e);
                } else {
                    float v[4];
                    #pragma unroll
                    for (int j = 0; j < 4; ++j) {
                        int acol = c4 + 4 + j;
                        if (X0 == 0) acol = max(acol, 12);
                        float av = S[OFF_GRAY + (r + 4) * 60 + acol];
                        float bv = S[OFF_GRAY + (r + 4) * 60 + c4 + 9 + j];
                        v[j] = av - bv;
                    }
                    o = make_float4(v[0], v[1], v[2], v[3]);
                }
                *(float4*)(S + OFF_A + r * 44 + c4) = o;
            } else {
                int r = k / 12, c4 = (k - r * 12) * 4;
                int arow = r + 4;
                if (BORDER && Y0 == 0) arow = max(arow, 12);
                float4 T = *(const float4*)(S + OFF_GRAY + arow * 60 + c4 + 4);
                float4 Bo = *(const float4*)(S + OFF_GRAY + (r + 9) * 60 + c4 + 4);
                *(float4*)(S + OFF_A + r * 48 + c4) =
                    make_float4(T.x - Bo.x, T.y - Bo.y, T.z - Bo.z, T.w - Bo.w);
            }
        }
    }
    __syncthreads();

    // ======== P3: pm2 (48x48 v 9-tap, masked 0 outside) + go (44x44) ========
    #pragma unroll
    for (int idx = tid; idx < 1060; idx += NT) {
        if (idx < 576) {
            int rg = idx / 48, c = idx - rg * 48;
            int r4 = rg * 4;
            float2 t[12];
            #pragma unroll
            for (int q = 0; q < 12; ++q) t[q] = S2[HM2 + (r4 + q) * 48 + c];
            float cx = fmaxf(fmaxf(fmaxf(t[3].x,t[4].x),fmaxf(t[5].x,t[6].x)),fmaxf(t[7].x,t[8].x));
            float cn = fminf(fminf(fminf(t[3].y,t[4].y),fminf(t[5].y,t[6].y)),fminf(t[7].y,t[8].y));
            float o0x = fmaxf(fmaxf(fmaxf(cx,t[0].x),t[1].x),t[2].x);
            float o1x = fmaxf(fmaxf(fmaxf(cx,t[1].x),t[2].x),t[9].x);
            float o2x = fmaxf(fmaxf(fmaxf(cx,t[2].x),t[9].x),t[10].x);
            float o3x = fmaxf(fmaxf(fmaxf(cx,t[9].x),t[10].x),t[11].x);
            float o0n = fminf(fminf(fminf(cn,t[0].y),t[1].y),t[2].y);
            float o1n = fminf(fminf(fminf(cn,t[1].y),t[2].y),t[9].y);
            float o2n = fminf(fminf(fminf(cn,t[2].y),t[9].y),t[10].y);
            float o3n = fminf(fminf(fminf(cn,t[9].y),t[10].y),t[11].y);
            if (BORDER) {
                int gx = X0 - 8 + c;
                bool inx = (unsigned)gx < (unsigned)W;
                int gyb = Y0 - 8 + r4;
                if (!(inx && (unsigned)(gyb+0)<(unsigned)H)) { o0x = 0.f; o0n = 0.f; }
                if (!(inx && (unsigned)(gyb+1)<(unsigned)H)) { o1x = 0.f; o1n = 0.f; }
                if (!(inx && (unsigned)(gyb+2)<(unsigned)H)) { o2x = 0.f; o2n = 0.f; }
                if (!(inx && (unsigned)(gyb+3)<(unsigned)H)) { o3x = 0.f; o3n = 0.f; }
            }
            S2[PM2 + (r4 + 0) * 48 + c] = make_float2(o0x, o0n);
            S2[PM2 + (r4 + 1) * 48 + c] = make_float2(o1x, o1n);
            S2[PM2 + (r4 + 2) * 48 + c] = make_float2(o2x, o2n);
            S2[PM2 + (r4 + 3) * 48 + c] = make_float2(o3x, o3n);
        } else {
            int k = idx - 576;    // 484 items -> go
            if (DIR == 0) {
                int rg = k / 44, c = k - rg * 44;
                int r4 = rg * 4;
                float t[8];
                #pragma unroll
                for (int q = 0; q < 8; ++q) t[q] = S[OFF_A + (r4 + q) * 44 + c];
                float s0 = t[0] + t[1] + t[2] + t[3] + t[4];
                float s1 = s0 - t[0] + t[5];
                float s2 = s1 - t[1] + t[6];
                float s3 = s2 - t[2] + t[7];
                float ss[4] = { s0, s1, s2, s3 };
                #pragma unroll
                for (int j = 0; j < 4; ++j) {
                    float v;
                    if (!BORDER) {
                        v = fabsf(ss[j] * 0.04f);
                    } else {
                        int gx = X0 - 6 + c, gy = Y0 - 6 + r4 + j;
                        if ((unsigned)gx < (unsigned)W && (unsigned)gy < (unsigned)H) {
                            float cntx = (float)(min(gx + 2, W - 1) - max(gx - 2, 0) + 1);
                            float cnty = (float)(min(gy + 2, H - 1) - max(gy - 2, 0) + 1);
                            v = fabsf(__fdividef(ss[j], cntx * cnty));
                        } else v = NANF;
                    }
                    S[OFF_GO + (r4 + j) * 44 + c] = v;
                }
            } else {
                int r = k / 11, c4 = (k - r * 11) * 4;
                float4 A = *(const float4*)(S + OFF_A + r * 48 + c4);
                float4 Bv = *(const float4*)(S + OFF_A + r * 48 + c4 + 4);
                float t0=A.x,t1=A.y,t2=A.z,t3=A.w,t4=Bv.x,t5=Bv.y,t6=Bv.z,t7=Bv.w;
                float s0 = t0 + t1 + t2 + t3 + t4;
                float s1 = s0 - t0 + t5;
                float s2 = s1 - t1 + t6;
                float s3 = s2 - t2 + t7;
                float ss[4] = { s0, s1, s2, s3 };
                float4 o;
                float* op = &o.x;
                #pragma unroll
                for (int j = 0; j < 4; ++j) {
                    float v;
                    if (!BORDER) {
                        v = fabsf(ss[j] * 0.04f);
                    } else {
                        int gx = X0 - 6 + c4 + j, gy = Y0 - 6 + r;
                        if ((unsigned)gx < (unsigned)W && (unsigned)gy < (unsigned)H) {
                            float cntx = (float)(min(gx + 2, W - 1) - max(gx - 2, 0) + 1);
                            float cnty = (float)(min(gy + 2, H - 1) - max(gy - 2, 0) + 1);
                            v = fabsf(__fdividef(ss[j], cntx * cnty));
                        } else v = NANF;
                    }
                    op[j] = v;
                }
                *(float4*)(S + OFF_GO + r * 44 + c4) = o;
            }
        }
    }
    __syncthreads();

    // ======== P4: h17f2 (48x32) from pm2 + h72 (44x38) from go ========
    #pragma unroll
    for (int idx = tid; idx < 824; idx += NT) {
        if (idx < 384) {
            int r = idx / 8, g4 = (idx & 7) * 4;
            const float4* p = (const float4*)(S2 + PM2 + r * 48 + g4);
            float ta[20], tb[20];
            #pragma unroll
            for (int q = 0; q < 10; ++q) {
                float4 v = p[q];
                ta[2*q] = v.x; tb[2*q] = v.y;
                ta[2*q+1] = v.z; tb[2*q+1] = v.w;
            }
            float a0 = 0.f, b0 = 0.f;
            #pragma unroll
            for (int q = 0; q < 17; ++q) { a0 += ta[q]; b0 += tb[q]; }
            float a1 = a0 - ta[0] + ta[17], b1 = b0 - tb[0] + tb[17];
            float a2 = a1 - ta[1] + ta[18], b2 = b1 - tb[1] + tb[18];
            float a3 = a2 - ta[2] + ta[19], b3 = b2 - tb[2] + tb[19];
            float4* dst = (float4*)(S2 + H17F2 + r * 32 + g4);
            dst[0] = make_float4(a0, b0, a1, b1);
            dst[1] = make_float4(a2, b2, a3, b3);
        } else {
            int k = idx - 384;     // 440 items
            int r = k / 10, g = k - r * 10;
            if (g < 9) {
                int g4 = g * 4;
                const float* p = S + OFF_GO + r * 44 + g4;
                float4 A = *(const float4*)p;
                float4 Bv = *(const float4*)(p + 4);
                float4 Cv = *(const float4*)(p + 8);
                float t0=A.x,t1=A.y,t2=A.z,t3=A.w,t4=Bv.x,t5=Bv.y,t6=Bv.z,t7=Bv.w,t8=Cv.x,t9=Cv.y;
                float cx = fmaxf(fmaxf(t3,t4),fmaxf(t5,t6));
                float cn = fminf(fminf(t3,t4),fminf(t5,t6));
                float ox0 = fmaxf(fmaxf(fmaxf(cx,t0),t1),t2);
                float ox1 = fmaxf(fmaxf(fmaxf(cx,t1),t2),t7);
                float ox2 = fmaxf(fmaxf(fmaxf(cx,t2),t7),t8);
                float ox3 = fmaxf(fmaxf(fmaxf(cx,t7),t8),t9);
                float on0 = fminf(fminf(fminf(cn,t0),t1),t2);
                float on1 = fminf(fminf(fminf(cn,t1),t2),t7);
                float on2 = fminf(fminf(fminf(cn,t2),t7),t8);
                float on3 = fminf(fminf(fminf(cn,t7),t8),t9);
                float4* dst = (float4*)(S2 + H72 + r * 40 + g4);
                dst[0] = make_float4(ox0, on0, ox1, on1);
                dst[1] = make_float4(ox2, on2, ox3, on3);
            } else {
                const float* p = S + OFF_GO + r * 44 + 36;
                float4 A = *(const float4*)p;
                float4 Bv = *(const float4*)(p + 4);
                float t0=A.x,t1=A.y,t2=A.z,t3=A.w,t4=Bv.x,t5=Bv.y,t6=Bv.z,t7=Bv.w;
                float c6x = fmaxf(fmaxf(t1,t2),fmaxf(fmaxf(t3,t4),fmaxf(t5,t6)));
                float c6n = fminf(fminf(t1,t2),fminf(fminf(t3,t4),fminf(t5,t6)));
                S2[H72 + r * 40 + 36] = make_float2(fmaxf(c6x, t0), fminf(c6n, t0));
                S2[H72 + r * 40 + 37] = make_float2(fmaxf(c6x, t7), fminf(c6n, t7));
            }
        }
    }
    __syncthreads();

    // ======== P5: v17 on tids 0-255 (regs) || m72 on tids 256-511 ========
    if (tid < 256) {
        int rg = tid >> 5, c = tid & 31;
        int r0 = rg * 4;
        float inv[4];
        if (!BORDER) {
            #pragma unroll
            for (int j = 0; j < 4; ++j) inv[j] = 1.f / 289.f;
        } else {
            int gx = X0 + c;
            float cntx = (float)(min(gx + 8, W - 1) - max(gx - 8, 0) + 1);
            #pragma unroll
            for (int j = 0; j < 4; ++j) {
                int gy = Y0 + r0 + j;
                float cnty = (float)(min(gy + 8, H - 1) - max(gy - 8, 0) + 1);
                inv[j] = __fdividef(1.f, cntx * cnty);
            }
        }
        float2 t[20];
        #pragma unroll
        for (int q = 0; q < 20; ++q) t[q] = S2[H17F2 + (r0 + q) * 32 + c];
        float sa = 0.f, sb = 0.f;
        #pragma unroll
        for (int q = 0; q < 17; ++q) { sa += t[q].x; sb += t[q].y; }
        gmv[0] = sa * inv[0]; gnv[0] = sb * inv[0];
        sa += t[17].x - t[0].x; sb += t[17].y - t[0].y;
        gmv[1] = sa * inv[1]; gnv[1] = sb * inv[1];
        sa += t[18].x - t[1].x; sb += t[18].y - t[1].y;
        gmv[2] = sa * inv[2]; gnv[2] = sb * inv[2];
        sa += t[19].x - t[2].x; sb += t[19].y - t[2].y;
        gmv[3] = sa * inv[3]; gnv[3] = sb * inv[3];
    } else {
        #pragma unroll
        for (int k = tid - 256; k < 380; k += 256) {
            int rg = k / 38, c = k - rg * 38;
            int r0 = min(rg * 4, 34);
            float2 t[10];
            #pragma unroll
            for (int q = 0; q < 10; ++q) t[q] = S2[H72 + (r0 + q) * 40 + c];
            float cx = fmaxf(fmaxf(t[3].x,t[4].x),fmaxf(t[5].x,t[6].x));
            float cn = fminf(fminf(t[3].y,t[4].y),fminf(t[5].y,t[6].y));
            float o0x = fmaxf(fmaxf(fmaxf(cx,t[0].x),t[1].x),t[2].x);
            float o1x = fmaxf(fmaxf(fmaxf(cx,t[1].x),t[2].x),t[7].x);
            float o2x = fmaxf(fmaxf(fmaxf(cx,t[2].x),t[7].x),t[8].x);
            float o3x = fmaxf(fmaxf(fmaxf(cx,t[7].x),t[8].x),t[9].x);
            float o0n = fminf(fminf(fminf(cn,t[0].y),t[1].y),t[2].y);
            float o1n = fminf(fminf(fminf(cn,t[1].y),t[2].y),t[7].y);
            float o2n = fminf(fminf(fminf(cn,t[2].y),t[7].y),t[8].y);
            float o3n = fminf(fminf(fminf(cn,t[7].y),t[8].y),t[9].y);
            if (BORDER) {
                int gx = X0 - 3 + c;
                bool inx = (unsigned)gx < (unsigned)W;
                int gyb = Y0 - 3 + r0;
                if (!(inx && (unsigned)(gyb+0)<(unsigned)H)) { o0x = 0.f; o0n = 0.f; }
                if (!(inx && (unsigned)(gyb+1)<(unsigned)H)) { o1x = 0.f; o1n = 0.f; }
                if (!(inx && (unsigned)(gyb+2)<(unsigned)H)) { o2x = 0.f; o2n = 0.f; }
                if (!(inx && (unsigned)(gyb+3)<(unsigned)H)) { o3x = 0.f; o3n = 0.f; }
            }
            S2[M72 + (r0 + 0) * 40 + c] = make_float2(o0x, o0n);
            S2[M72 + (r0 + 1) * 40 + c] = make_float2(o1x, o1n);
            S2[M72 + (r0 + 2) * 40 + c] = make_float2(o2x, o2n);
            S2[M72 + (r0 + 3) * 40 + c] = make_float2(o3x, o3n);
        }
    }
    __syncthreads();

    // ======== P6: h7s2 (38x32) 7-tap h-sums of m72 ========
    #pragma unroll
    for (int idx = tid; idx < 304; idx += NT) {
        int r = idx / 8, g4 = (idx & 7) * 4;
        const float4* p = (const float4*)(S2 + M72 + r * 40 + g4);
        float ta[10], tb[10];
        #pragma unroll
        for (int q = 0; q < 5; ++q) {
            float4 v = p[q];
            ta[2*q] = v.x; tb[2*q] = v.y;
            ta[2*q+1] = v.z; tb[2*q+1] = v.w;
        }
        float a0 = ta[0]+ta[1]+ta[2]+ta[3]+ta[4]+ta[5]+ta[6];
        float b0 = tb[0]+tb[1]+tb[2]+tb[3]+tb[4]+tb[5]+tb[6];
        float a1 = a0 - ta[0] + ta[7], b1 = b0 - tb[0] + tb[7];
        float a2 = a1 - ta[1] + ta[8], b2 = b1 - tb[1] + tb[8];
        float a3 = a2 - ta[2] + ta[9], b3 = b2 - tb[2] + tb[9];
        float4* dst = (float4*)(S2 + H7S2 + r * 32 + g4);
        dst[0] = make_float4(a0, b0, a1, b1);
        dst[1] = make_float4(a2, b2, a3, b3);
    }
    __syncthreads();

    // ======== P7: final (32x32), tid<256 ========
    if (tid < 256) {
        int rg = tid >> 5, c = tid & 31;
        int r0 = rg * 4;
        float2 t[10];
        #pragma unroll
        for (int q = 0; q < 10; ++q) t[q] = S2[H7S2 + (r0 + q) * 32 + c];
        float sA[4], sD[4];
        sA[0] = t[0].x+t[1].x+t[2].x+t[3].x+t[4].x+t[5].x+t[6].x;
        sD[0] = t[0].y+t[1].y+t[2].y+t[3].y+t[4].y+t[5].y+t[6].y;
        sA[1] = sA[0] - t[0].x + t[7].x; sD[1] = sD[0] - t[0].y + t[7].y;
        sA[2] = sA[1] - t[1].x + t[8].x; sD[2] = sD[1] - t[1].y + t[8].y;
        sA[3] = sA[2] - t[2].x + t[9].x; sD[3] = sD[2] - t[2].y + t[9].y;
        #pragma unroll
        for (int j = 0; j < 4; ++j) {
            float inv;
            if (!BORDER) {
                inv = 1.f / 49.f;
            } else {
                int gx = X0 + c, gy = Y0 + r0 + j;
                float cntx = (float)(min(gx + 3, W - 1) - max(gx - 3, 0) + 1);
                float cnty = (float)(min(gy + 3, H - 1) - max(gy - 3, 0) + 1);
                inv = __fdividef(1.f, cntx * cnty);
            }
            float pmax = sA[j] * inv, pmin = sD[j] * inv;
            float go = S[OFF_GO + (r0 + j + 6) * 44 + c + 6];
            float ga = S[OFF_SGA + (r0 + j + 12) * 56 + c + 12];
            float gn = __fdividef(go - pmin, fabsf(pmax - pmin) + EPSF);
            float gn1 = __fdividef(ga - gnv[j], fabsf(gmv[j] - gnv[j]) + EPSF);
            float val = (gn + 0.01f) * gn1;
            if (mode == 0) {
                vsave[j] = val;
            } else {
                float rv = vsave[j];
                acc += (double)(rv * expf(-10.f * (rv + val)));
            }
        }
    }
    __syncthreads();
}

template<bool BORDER>
__device__ __forceinline__ void run(float* S, int X0, int Y0, int b, int tid, double& acc)
{
    float vsx[4], vsy[4];
    #pragma unroll
    for (int img = 0; img < 2; ++img) {
        const float* __restrict__ gp = g_gray + (size_t)img * NMAP + (size_t)b * NPIX;
        if (!BORDER) {
            #pragma unroll
            for (int idx = tid; idx < 870; idx += NT) {
                int r = idx / 15, c4 = (idx - r * 15) * 4;
                float4 v = *(const float4*)(gp + (Y0 - 12 + r) * W + X0 - 12 + c4);
                *(float4*)(S + OFF_GRAY + r * 60 + c4) = v;
            }
        } else {
            for (int idx = tid; idx < 3364; idx += NT) {
                int r = idx / 58, c = idx - r * 58;
                int gy = Y0 - 12 + r, gx = X0 - 12 + c;
                float v = 0.f;
                if ((unsigned)gx < (unsigned)W && (unsigned)gy < (unsigned)H)
                    v = __ldg(gp + gy * W + gx);
                S[OFF_GRAY + r * 60 + c] = v;
            }
        }
        __syncthreads();
        pipe<0, BORDER>(S, X0, Y0, tid, img, vsx, acc);
        pipe<1, BORDER>(S, X0, Y0, tid, img, vsy, acc);
    }
}

__global__ __launch_bounds__(NT, 2)
void k_mega() {
    extern __shared__ float S[];
    __shared__ double sred[NT / 32];

    const int b = blockIdx.z;
    const int X0 = blockIdx.x * 32, Y0 = blockIdx.y * 32;
    const int tid = threadIdx.x;

    double acc = 0.0;
    bool border = (blockIdx.x == 0) | (blockIdx.x == 15) | (blockIdx.y == 0) | (blockIdx.y == 15);
    if (border) run<true>(S, X0, Y0, b, tid, acc);
    else        run<false>(S, X0, Y0, b, tid, acc);

    int tx = tid & 31, ty = tid >> 5;
    #pragma unroll
    for (int off = 16; off; off >>= 1) acc += __shfl_down_sync(0xffffffffu, acc, off);
    if (tx == 0) sred[ty] = acc;
    __syncthreads();
    if (ty == 0 && tx < NT / 32) {
        double w = sred[tx];
        #pragma unroll
        for (int off = (NT / 64); off; off >>= 1) w += __shfl_down_sync(0xffffffffu, w, off);
        if (tx == 0) atomicAdd(&g_acc, w);
    }
}

__global__ void k_out(float* __restrict__ out) {
    out[0] = (float)(g_acc / (double)NMAP);
}

extern "C" void kernel_launch(void* const* d_in, const int* in_sizes, int n_in,
                              void* d_out, int out_size) {
    const float* R_low = (const float*)d_in[0];
    const float* low = (const float*)d_in[1];
    float* out = (float*)d_out;

    cudaFuncSetAttribute(k_mega, cudaFuncAttributeMaxDynamicSharedMemorySize, SMEM_BYTES);

    float* grayR;
    cudaGetSymbolAddress((void**)&grayR, g_gray);
    float* grayL = grayR + NMAP;

    int gray_blocks = (NMAP / 4 + 255) / 256;

    k_zero<<<1, 1>>>();
    k_gray<<<gray_blocks, 256>>>(R_low, grayR);
    k_gray<<<gray_blocks, 256>>>(low, grayL);

    dim3 grd(16, 16, 16);
    k_mega<<<grd, NT, SMEM_BYTES>>>();

    k_out<<<1, 1>>>(out);
}

// round 14
// speedup vs baseline: 1.1106x; 1.1106x over previous
#include <cuda_runtime.h>
#include <math.h>

#define W 512
#define H 512
#define BATCH 16
#define NPIX (W*H)
#define NMAP (BATCH*NPIX)
#define EPSF 1e-4f
#define NT 512

#define NANF __int_as_float(0x7fffffff)

__device__ float g_gray[2 * NMAP];
__device__ double g_acc;

// ---- smem layout (floats) ----
// gray 58x58 s60 @0 (3480) ; sga 56x56 s56 @3480 (3136) ; go 44x44 s44 @6616 (1936)
// A @8552 (3520): hs5/vs5 (2112) -> h7x/h7n (2x1760) -> h7s (2x1216)
// B @12072 (5376): hm (2x2688) -> h17 (2x1536)
// C @17448 (4608): pm (2x2304) -> m7 (2x1520)
#define OFF_GRAY 0
#define OFF_SGA  3480
#define OFF_GO   6616
#define OFF_A    8552
#define OFF_B    12072
#define OFF_C    17448
#define SMEM_FLOATS 22056
#define SMEM_BYTES (SMEM_FLOATS * 4)

__global__ void k_zero() { g_acc = 0.0; }

__global__ void k_gray(const float* __restrict__ in, float* __restrict__ outp) {
    int i = blockIdx.x * blockDim.x + threadIdx.x;
    if (i >= NMAP / 4) return;
    int b = i / (NPIX / 4);
    int p = i - b * (NPIX / 4);
    const float4* base = (const float4*)(in + (size_t)b * 3 * NPIX);
    float4 r = base[p];
    float4 g = base[NPIX / 4 + p];
    float4 bl = base[2 * (NPIX / 4) + p];
    float4 o;
    o.x = 0.299f * r.x + 0.587f * g.x + 0.114f * bl.x;
    o.y = 0.299f * r.y + 0.587f * g.y + 0.114f * bl.y;
    o.z = 0.299f * r.z + 0.587f * g.z + 0.114f * bl.z;
    o.w = 0.299f * r.w + 0.587f * g.w + 0.114f * bl.w;
    ((float4*)outp)[i] = o;
}

template<int DIR, bool BORDER>
__device__ __forceinline__ void pipe(float* S, int X0, int Y0, int tid,
                                     int mode, float* vsave, double& acc)
{
    float gmv[4], gnv[4];

    // ======== P1: sga (56x56) |grad|, NaN outside (border only) ========
    #pragma unroll
    for (int idx = tid; idx < 784; idx += NT) {
        int r = idx / 14, g4 = (idx - r * 14) * 4;
        const float* p = S + OFF_GRAY + r * 60 + g4;
        float4 a = *(const float4*)p;
        float n0, n1, n2, n3;
        if (DIR == 0) {
            float e = p[4];
            n0 = a.y; n1 = a.z; n2 = a.w; n3 = e;
        } else {
            float4 bb = *(const float4*)(p + 60);
            n0 = bb.x; n1 = bb.y; n2 = bb.z; n3 = bb.w;
        }
        float4 o;
        o.x = fabsf(a.x - n0); o.y = fabsf(a.y - n1);
        o.z = fabsf(a.z - n2); o.w = fabsf(a.w - n3);
        if (BORDER) {
            int gy = Y0 - 12 + r, gxb = X0 - 12 + g4;
            bool iny = (unsigned)gy < (unsigned)H;
            if (!(iny && (unsigned)(gxb + 0) < (unsigned)W)) o.x = NANF;
            if (!(iny && (unsigned)(gxb + 1) < (unsigned)W)) o.y = NANF;
            if (!(iny && (unsigned)(gxb + 2) < (unsigned)W)) o.z = NANF;
            if (!(iny && (unsigned)(gxb + 3) < (unsigned)W)) o.w = NANF;
        }
        *(float4*)(S + OFF_SGA + r * 56 + g4) = o;
    }
    __syncthreads();

    // ======== P2: hm (56x48) + telescoped hs5/vs5 ========
    #pragma unroll
    for (int idx = tid; idx < 1200; idx += NT) {
        if (idx < 672) {
            int r = idx / 12, g4 = (idx - r * 12) * 4;
            const float* p = S + OFF_SGA + r * 56 + g4;
            float4 A = *(const float4*)p;
            float4 Bv = *(const float4*)(p + 4);
            float4 Cv = *(const float4*)(p + 8);
            float t0=A.x,t1=A.y,t2=A.z,t3=A.w,t4=Bv.x,t5=Bv.y,t6=Bv.z,t7=Bv.w,t8=Cv.x,t9=Cv.y,t10=Cv.z,t11=Cv.w;
            float cx = fmaxf(fmaxf(fmaxf(t3,t4),fmaxf(t5,t6)),fmaxf(t7,t8));
            float cn = fminf(fminf(fminf(t3,t4),fminf(t5,t6)),fminf(t7,t8));
            float4 ox, on;
            ox.x = fmaxf(fmaxf(fmaxf(cx,t0),t1),t2);
            ox.y = fmaxf(fmaxf(fmaxf(cx,t1),t2),t9);
            ox.z = fmaxf(fmaxf(fmaxf(cx,t2),t9),t10);
            ox.w = fmaxf(fmaxf(fmaxf(cx,t9),t10),t11);
            on.x = fminf(fminf(fminf(cn,t0),t1),t2);
            on.y = fminf(fminf(fminf(cn,t1),t2),t9);
            on.z = fminf(fminf(fminf(cn,t2),t9),t10);
            on.w = fminf(fminf(fminf(cn,t9),t10),t11);
            *(float4*)(S + OFF_B + r * 48 + g4) = ox;
            *(float4*)(S + OFF_B + 2688 + r * 48 + g4) = on;
        } else {
            int k = idx - 672;    // 528 items
            if (DIR == 0) {
                // hs5: 48 rows x 44 cols (stride 44). hs5 = gray[gx-2] - gray[gx+3]
                int r = k / 11, c4 = (k - r * 11) * 4;
                float4 o;
                if (!BORDER) {
                    const float* p = S + OFF_GRAY + (r + 4) * 60 + c4;
                    float4 A = *(const float4*)(p + 4);
                    float4 Bv = *(const float4*)(p + 8);
                    float e = p[12];
                    o = make_float4(A.x - Bv.y, A.y - Bv.z, A.z - Bv.w, A.w - e);
                } else {
                    float v[4];
                    #pragma unroll
                    for (int j = 0; j < 4; ++j) {
                        int acol = c4 + 4 + j;
                        if (X0 == 0) acol = max(acol, 12);
                        float av = S[OFF_GRAY + (r + 4) * 60 + acol];
                        float bv = S[OFF_GRAY + (r + 4) * 60 + c4 + 9 + j];
                        v[j] = av - bv;
                    }
                    o = make_float4(v[0], v[1], v[2], v[3]);
                }
                *(float4*)(S + OFF_A + r * 44 + c4) = o;
            } else {
                // vs5: 44 rows x 48 cols (stride 48). vs5 = gray[gy-2] - gray[gy+3]
                int r = k / 12, c4 = (k - r * 12) * 4;
                int arow = r + 4;
                if (BORDER && Y0 == 0) arow = max(arow, 12);
                float4 T = *(const float4*)(S + OFF_GRAY + arow * 60 + c4 + 4);
                float4 Bo = *(const float4*)(S + OFF_GRAY + (r + 9) * 60 + c4 + 4);
                *(float4*)(S + OFF_A + r * 48 + c4) =
                    make_float4(T.x - Bo.x, T.y - Bo.y, T.z - Bo.z, T.w - Bo.w);
            }
        }
    }
    __syncthreads();

    // ======== P3: pm (48x48, masked 0 outside) + go (44x44) ========
    #pragma unroll
    for (int idx = tid; idx < 1060; idx += NT) {
        if (idx < 576) {
            int rg = idx / 48, c = idx - rg * 48;
            int r4 = rg * 4;
            {
                float t[12];
                #pragma unroll
                for (int q = 0; q < 12; ++q) t[q] = S[OFF_B + (r4 + q) * 48 + c];
                float cx = fmaxf(fmaxf(fmaxf(t[3],t[4]),fmaxf(t[5],t[6])),fmaxf(t[7],t[8]));
                float o0 = fmaxf(fmaxf(fmaxf(cx,t[0]),t[1]),t[2]);
                float o1 = fmaxf(fmaxf(fmaxf(cx,t[1]),t[2]),t[9]);
                float o2 = fmaxf(fmaxf(fmaxf(cx,t[2]),t[9]),t[10]);
                float o3 = fmaxf(fmaxf(fmaxf(cx,t[9]),t[10]),t[11]);
                if (BORDER) {
                    int gx = X0 - 8 + c;
                    bool inx = (unsigned)gx < (unsigned)W;
                    int gyb = Y0 - 8 + r4;
                    if (!(inx && (unsigned)(gyb+0)<(unsigned)H)) o0 = 0.f;
                    if (!(inx && (unsigned)(gyb+1)<(unsigned)H)) o1 = 0.f;
                    if (!(inx && (unsigned)(gyb+2)<(unsigned)H)) o2 = 0.f;
                    if (!(inx && (unsigned)(gyb+3)<(unsigned)H)) o3 = 0.f;
                }
                S[OFF_C + (r4 + 0) * 48 + c] = o0;
                S[OFF_C + (r4 + 1) * 48 + c] = o1;
                S[OFF_C + (r4 + 2) * 48 + c] = o2;
                S[OFF_C + (r4 + 3) * 48 + c] = o3;
            }
            {
                float t[12];
                #pragma unroll
                for (int q = 0; q < 12; ++q) t[q] = S[OFF_B + 2688 + (r4 + q) * 48 + c];
                float cn = fminf(fminf(fminf(t[3],t[4]),fminf(t[5],t[6])),fminf(t[7],t[8]));
                float o0 = fminf(fminf(fminf(cn,t[0]),t[1]),t[2]);
                float o1 = fminf(fminf(fminf(cn,t[1]),t[2]),t[9]);
                float o2 = fminf(fminf(fminf(cn,t[2]),t[9]),t[10]);
                float o3 = fminf(fminf(fminf(cn,t[9]),t[10]),t[11]);
                if (BORDER) {
                    int gx = X0 - 8 + c;
                    bool inx = (unsigned)gx < (unsigned)W;
                    int gyb = Y0 - 8 + r4;
                    if (!(inx && (unsigned)(gyb+0)<(unsigned)H)) o0 = 0.f;
                    if (!(inx && (unsigned)(gyb+1)<(unsigned)H)) o1 = 0.f;
                    if (!(inx && (unsigned)(gyb+2)<(unsigned)H)) o2 = 0.f;
                    if (!(inx && (unsigned)(gyb+3)<(unsigned)H)) o3 = 0.f;
                }
                S[OFF_C + 2304 + (r4 + 0) * 48 + c] = o0;
                S[OFF_C + 2304 + (r4 + 1) * 48 + c] = o1;
                S[OFF_C + 2304 + (r4 + 2) * 48 + c] = o2;
                S[OFF_C + 2304 + (r4 + 3) * 48 + c] = o3;
            }
        } else {
            int k = idx - 576;    // 484 items -> go
            if (DIR == 0) {
                int rg = k / 44, c = k - rg * 44;
                int r4 = rg * 4;
                float t[8];
                #pragma unroll
                for (int q = 0; q < 8; ++q) t[q] = S[OFF_A + (r4 + q) * 44 + c];
                float s0 = t[0] + t[1] + t[2] + t[3] + t[4];
                float s1 = s0 - t[0] + t[5];
                float s2 = s1 - t[1] + t[6];
                float s3 = s2 - t[2] + t[7];
                float ss[4] = { s0, s1, s2, s3 };
                #pragma unroll
                for (int j = 0; j < 4; ++j) {
                    float v;
                    if (!BORDER) {
                        v = fabsf(ss[j] * 0.04f);
                    } else {
                        int gx = X0 - 6 + c, gy = Y0 - 6 + r4 + j;
                        if ((unsigned)gx < (unsigned)W && (unsigned)gy < (unsigned)H) {
                            float cntx = (float)(min(gx + 2, W - 1) - max(gx - 2, 0) + 1);
                            float cnty = (float)(min(gy + 2, H - 1) - max(gy - 2, 0) + 1);
                            v = fabsf(__fdividef(ss[j], cntx * cnty));
                        } else v = NANF;
                    }
                    S[OFF_GO + (r4 + j) * 44 + c] = v;
                }
            } else {
                int r = k / 11, c4 = (k - r * 11) * 4;
                float4 A = *(const float4*)(S + OFF_A + r * 48 + c4);
                float4 Bv = *(const float4*)(S + OFF_A + r * 48 + c4 + 4);
                float t0=A.x,t1=A.y,t2=A.z,t3=A.w,t4=Bv.x,t5=Bv.y,t6=Bv.z,t7=Bv.w;
                float s0 = t0 + t1 + t2 + t3 + t4;
                float s1 = s0 - t0 + t5;
                float s2 = s1 - t1 + t6;
                float s3 = s2 - t2 + t7;
                float ss[4] = { s0, s1, s2, s3 };
                float4 o;
                float* op = &o.x;
                #pragma unroll
                for (int j = 0; j < 4; ++j) {
                    float v;
                    if (!BORDER) {
                        v = fabsf(ss[j] * 0.04f);
                    } else {
                        int gx = X0 - 6 + c4 + j, gy = Y0 - 6 + r;
                        if ((unsigned)gx < (unsigned)W && (unsigned)gy < (unsigned)H) {
                            float cntx = (float)(min(gx + 2, W - 1) - max(gx - 2, 0) + 1);
                            float cnty = (float)(min(gy + 2, H - 1) - max(gy - 2, 0) + 1);
                            v = fabsf(__fdividef(ss[j], cntx * cnty));
                        } else v = NANF;
                    }
                    op[j] = v;
                }
                *(float4*)(S + OFF_GO + r * 44 + c4) = o;
            }
        }
    }
    __syncthreads();

    // ======== P4: h17 (48x32) + h7 (44x38) ========
    #pragma unroll
    for (int idx = tid; idx < 824; idx += NT) {
        if (idx < 384) {
            int r = idx / 8, g4 = (idx & 7) * 4;
            #pragma unroll
            for (int arr = 0; arr < 2; ++arr) {
                const float* p = S + OFF_C + arr * 2304 + r * 48 + g4;
                float t[20];
                #pragma unroll
                for (int q = 0; q < 5; ++q) {
                    float4 v = *(const float4*)(p + q * 4);
                    t[q*4] = v.x; t[q*4+1] = v.y; t[q*4+2] = v.z; t[q*4+3] = v.w;
                }
                float s0 = 0.f;
                #pragma unroll
                for (int q = 0; q < 17; ++q) s0 += t[q];
                float s1 = s0 - t[0] + t[17];
                float s2 = s1 - t[1] + t[18];
                float s3 = s2 - t[2] + t[19];
                *(float4*)(S + OFF_B + arr * 1536 + r * 32 + g4) = make_float4(s0, s1, s2, s3);
            }
        } else {
            int k = idx - 384;     // 440 items
            int r = k / 10, g = k - r * 10;
            if (g < 9) {
                int g4 = g * 4;
                const float* p = S + OFF_GO + r * 44 + g4;
                float4 A = *(const float4*)p;
                float4 Bv = *(const float4*)(p + 4);
                float4 Cv = *(const float4*)(p + 8);
                float t0=A.x,t1=A.y,t2=A.z,t3=A.w,t4=Bv.x,t5=Bv.y,t6=Bv.z,t7=Bv.w,t8=Cv.x,t9=Cv.y;
                float cx = fmaxf(fmaxf(t3,t4),fmaxf(t5,t6));
                float cn = fminf(fminf(t3,t4),fminf(t5,t6));
                float4 ox, on;
                ox.x = fmaxf(fmaxf(fmaxf(cx,t0),t1),t2);
                ox.y = fmaxf(fmaxf(fmaxf(cx,t1),t2),t7);
                ox.z = fmaxf(fmaxf(fmaxf(cx,t2),t7),t8);
                ox.w = fmaxf(fmaxf(fmaxf(cx,t7),t8),t9);
                on.x = fminf(fminf(fminf(cn,t0),t1),t2);
                on.y = fminf(fminf(fminf(cn,t1),t2),t7);
                on.z = fminf(fminf(fminf(cn,t2),t7),t8);
                on.w = fminf(fminf(fminf(cn,t7),t8),t9);
                *(float4*)(S + OFF_A + r * 40 + g4) = ox;
                *(float4*)(S + OFF_A + 1760 + r * 40 + g4) = on;
            } else {
                const float* p = S + OFF_GO + r * 44 + 36;
                float4 A = *(const float4*)p;
                float4 Bv = *(const float4*)(p + 4);
                float t0=A.x,t1=A.y,t2=A.z,t3=A.w,t4=Bv.x,t5=Bv.y,t6=Bv.z,t7=Bv.w;
                float c6x = fmaxf(fmaxf(t1,t2),fmaxf(fmaxf(t3,t4),fmaxf(t5,t6)));
                float c6n = fminf(fminf(t1,t2),fminf(fminf(t3,t4),fminf(t5,t6)));
                S[OFF_A + r * 40 + 36] = fmaxf(c6x, t0);
                S[OFF_A + r * 40 + 37] = fmaxf(c6x, t7);
                S[OFF_A + 1760 + r * 40 + 36] = fminf(c6n, t0);
                S[OFF_A + 1760 + r * 40 + 37] = fminf(c6n, t7);
            }
        }
    }
    __syncthreads();

    // ======== P5: v17 -> regs on tids 0-255  ||  m7 (38x38, masked) on tids 256-511 ========
    if (tid < 256) {
        int rg = tid >> 5, c = tid & 31;
        int r0 = rg * 4;
        float inv[4];
        if (!BORDER) {
            #pragma unroll
            for (int j = 0; j < 4; ++j) inv[j] = 1.f / 289.f;
        } else {
            int gx = X0 + c;
            float cntx = (float)(min(gx + 8, W - 1) - max(gx - 8, 0) + 1);
            #pragma unroll
            for (int j = 0; j < 4; ++j) {
                int gy = Y0 + r0 + j;
                float cnty = (float)(min(gy + 8, H - 1) - max(gy - 8, 0) + 1);
                inv[j] = __fdividef(1.f, cntx * cnty);
            }
        }
        {
            float t[20];
            #pragma unroll
            for (int q = 0; q < 20; ++q) t[q] = S[OFF_B + (r0 + q) * 32 + c];
            float s0 = 0.f;
            #pragma unroll
            for (int q = 0; q < 17; ++q) s0 += t[q];
            float s1 = s0 - t[0] + t[17];
            float s2 = s1 - t[1] + t[18];
            float s3 = s2 - t[2] + t[19];
            gmv[0] = s0 * inv[0]; gmv[1] = s1 * inv[1];
            gmv[2] = s2 * inv[2]; gmv[3] = s3 * inv[3];
        }
        {
            float t[20];
            #pragma unroll
            for (int q = 0; q < 20; ++q) t[q] = S[OFF_B + 1536 + (r0 + q) * 32 + c];
            float s0 = 0.f;
            #pragma unroll
            for (int q = 0; q < 17; ++q) s0 += t[q];
            float s1 = s0 - t[0] + t[17];
            float s2 = s1 - t[1] + t[18];
            float s3 = s2 - t[2] + t[19];
            gnv[0] = s0 * inv[0]; gnv[1] = s1 * inv[1];
            gnv[2] = s2 * inv[2]; gnv[3] = s3 * inv[3];
        }
    } else {
        #pragma unroll
        for (int k = tid - 256; k < 380; k += 256) {
            int rg = k / 38, c = k - rg * 38;
            int r0 = min(rg * 4, 34);
            #pragma unroll
            for (int arr = 0; arr < 2; ++arr) {
                float t[10];
                #pragma unroll
                for (int q = 0; q < 10; ++q) t[q] = S[OFF_A + arr * 1760 + (r0 + q) * 40 + c];
                float o0, o1, o2, o3;
                if (arr == 0) {
                    float cx = fmaxf(fmaxf(t[3],t[4]),fmaxf(t[5],t[6]));
                    o0 = fmaxf(fmaxf(fmaxf(cx,t[0]),t[1]),t[2]);
                    o1 = fmaxf(fmaxf(fmaxf(cx,t[1]),t[2]),t[7]);
                    o2 = fmaxf(fmaxf(fmaxf(cx,t[2]),t[7]),t[8]);
                    o3 = fmaxf(fmaxf(fmaxf(cx,t[7]),t[8]),t[9]);
                } else {
                    float cn = fminf(fminf(t[3],t[4]),fminf(t[5],t[6]));
                    o0 = fminf(fminf(fminf(cn,t[0]),t[1]),t[2]);
                    o1 = fminf(fminf(fminf(cn,t[1]),t[2]),t[7]);
                    o2 = fminf(fminf(fminf(cn,t[2]),t[7]),t[8]);
                    o3 = fminf(fminf(fminf(cn,t[7]),t[8]),t[9]);
                }
                if (BORDER) {
                    int gx = X0 - 3 + c;
                    bool inx = (unsigned)gx < (unsigned)W;
                    int gyb = Y0 - 3 + r0;
                    if (!(inx && (unsigned)(gyb+0)<(unsigned)H)) o0 = 0.f;
                    if (!(inx && (unsigned)(gyb+1)<(unsigned)H)) o1 = 0.f;
                    if (!(inx && (unsigned)(gyb+2)<(unsigned)H)) o2 = 0.f;
                    if (!(inx && (unsigned)(gyb+3)<(unsigned)H)) o3 = 0.f;
                }
                S[OFF_C + arr * 1520 + (r0 + 0) * 40 + c] = o0;
                S[OFF_C + arr * 1520 + (r0 + 1) * 40 + c] = o1;
                S[OFF_C + arr * 1520 + (r0 + 2) * 40 + c] = o2;
                S[OFF_C + arr * 1520 + (r0 + 3) * 40 + c] = o3;
            }
        }
    }
    __syncthreads();

    // ======== P6: h7s (38x32) ========
    #pragma unroll
    for (int idx = tid; idx < 304; idx += NT) {
        int r = idx / 8, g4 = (idx & 7) * 4;
        #pragma unroll
        for (int arr = 0; arr < 2; ++arr) {
            const float* p = S + OFF_C + arr * 1520 + r * 40 + g4;
            float4 A = *(const float4*)p;
            float4 Bv = *(const float4*)(p + 4);
            float4 Cv = *(const float4*)(p + 8);
            float t0=A.x,t1=A.y,t2=A.z,t3=A.w,t4=Bv.x,t5=Bv.y,t6=Bv.z,t7=Bv.w,t8=Cv.x,t9=Cv.y;
            float s0 = t0+t1+t2+t3+t4+t5+t6;
            float s1 = s0 - t0 + t7;
            float s2 = s1 - t1 + t8;
            float s3 = s2 - t2 + t9;
            *(float4*)(S + OFF_A + arr * 1216 + r * 32 + g4) = make_float4(s0, s1, s2, s3);
        }
    }
    __syncthreads();

    // ======== P7: final (32x32) ========
    if (tid < 256) {
        int rg = tid >> 5, c = tid & 31;
        int r0 = rg * 4;
        float sA[4], sD[4];
        {
            float t[10];
            #pragma unroll
            for (int q = 0; q < 10; ++q) t[q] = S[OFF_A + (r0 + q) * 32 + c];
            sA[0] = t[0]+t[1]+t[2]+t[3]+t[4]+t[5]+t[6];
            sA[1] = sA[0] - t[0] + t[7];
            sA[2] = sA[1] - t[1] + t[8];
            sA[3] = sA[2] - t[2] + t[9];
        }
        {
            float t[10];
            #pragma unroll
            for (int q = 0; q < 10; ++q) t[q] = S[OFF_A + 1216 + (r0 + q) * 32 + c];
            sD[0] = t[0]+t[1]+t[2]+t[3]+t[4]+t[5]+t[6];
            sD[1] = sD[0] - t[0] + t[7];
            sD[2] = sD[1] - t[1] + t[8];
            sD[3] = sD[2] - t[2] + t[9];
        }
        #pragma unroll
        for (int j = 0; j < 4; ++j) {
            float inv;
            if (!BORDER) {
                inv = 1.f / 49.f;
            } else {
                int gx = X0 + c, gy = Y0 + r0 + j;
                float cntx = (float)(min(gx + 3, W - 1) - max(gx - 3, 0) + 1);
                float cnty = (float)(min(gy + 3, H - 1) - max(gy - 3, 0) + 1);
                inv = __fdividef(1.f, cntx * cnty);
            }
            float pmax = sA[j] * inv, pmin = sD[j] * inv;
            float go = S[OFF_GO + (r0 + j + 6) * 44 + c + 6];
            float ga = S[OFF_SGA + (r0 + j + 12) * 56 + c + 12];
            float gn = __fdividef(go - pmin, fabsf(pmax - pmin) + EPSF);
            float gn1 = __fdividef(ga - gnv[j], fabsf(gmv[j] - gnv[j]) + EPSF);
            float val = (gn + 0.01f) * gn1;
            if (mode == 0) {
                vsave[j] = val;
            } else {
                float rv = vsave[j];
                acc += (double)(rv * expf(-10.f * (rv + val)));
            }
        }
    }
    __syncthreads();
}

template<bool BORDER>
__device__ __forceinline__ void run(float* S, int X0, int Y0, int b, int tid, double& acc)
{
    float vsx[4], vsy[4];
    #pragma unroll
    for (int img = 0; img < 2; ++img) {
        const float* __restrict__ gp = g_gray + (size_t)img * NMAP + (size_t)b * NPIX;
        if (!BORDER) {
            #pragma unroll
            for (int idx = tid; idx < 870; idx += NT) {
                int r = idx / 15, c4 = (idx - r * 15) * 4;
                float4 v = *(const float4*)(gp + (Y0 - 12 + r) * W + X0 - 12 + c4);
                *(float4*)(S + OFF_GRAY + r * 60 + c4) = v;
            }
        } else {
            for (int idx = tid; idx < 3364; idx += NT) {
                int r = idx / 58, c = idx - r * 58;
                int gy = Y0 - 12 + r, gx = X0 - 12 + c;
                float v = 0.f;
                if ((unsigned)gx < (unsigned)W && (unsigned)gy < (unsigned)H)
                    v = __ldg(gp + gy * W + gx);
                S[OFF_GRAY + r * 60 + c] = v;
            }
        }
        __syncthreads();
        pipe<0, BORDER>(S, X0, Y0, tid, img, vsx, acc);
        pipe<1, BORDER>(S, X0, Y0, tid, img, vsy, acc);
    }
}

__global__ __launch_bounds__(NT, 2)
void k_mega() {
    extern __shared__ float S[];
    __shared__ double sred[NT / 32];

    const int b = blockIdx.z;
    const int X0 = blockIdx.x * 32, Y0 = blockIdx.y * 32;
    const int tid = threadIdx.x;

    double acc = 0.0;
    bool border = (blockIdx.x == 0) | (blockIdx.x == 15) | (blockIdx.y == 0) | (blockIdx.y == 15);
    if (border) run<true>(S, X0, Y0, b, tid, acc);
    else        run<false>(S, X0, Y0, b, tid, acc);

    int tx = tid & 31, ty = tid >> 5;
    #pragma unroll
    for (int off = 16; off; off >>= 1) acc += __shfl_down_sync(0xffffffffu, acc, off);
    if (tx == 0) sred[ty] = acc;
    __syncthreads();
    if (ty == 0 && tx < NT / 32) {
        double w = sred[tx];
        #pragma unroll
        for (int off = (NT / 64); off; off >>= 1) w += __shfl_down_sync(0xffffffffu, w, off);
        if (tx == 0) atomicAdd(&g_acc, w);
    }
}

__global__ void k_out(float* __restrict__ out) {
    out[0] = (float)(g_acc / (double)NMAP);
}

extern "C" void kernel_launch(void* const* d_in, const int* in_sizes, int n_in,
                              void* d_out, int out_size) {
    const float* R_low = (const float*)d_in[0];
    const float* low = (const float*)d_in[1];
    float* out = (float*)d_out;

    cudaFuncSetAttribute(k_mega, cudaFuncAttributeMaxDynamicSharedMemorySize, SMEM_BYTES);

    float* grayR;
    cudaGetSymbolAddress((void**)&grayR, g_gray);
    float* grayL = grayR + NMAP;

    int gray_blocks = (NMAP / 4 + 255) / 256;

    k_zero<<<1, 1>>>();
    k_gray<<<gray_blocks, 256>>>(R_low, grayR);
    k_gray<<<gray_blocks, 256>>>(low, grayL);

    dim3 grd(16, 16, 16);
    k_mega<<<grd, NT, SMEM_BYTES>>>();

    k_out<<<1, 1>>>(out);
}

// round 15
// speedup vs baseline: 1.1579x; 1.0426x over previous
#include <cuda_runtime.h>
#include <math.h>

#define W 512
#define H 512
#define BATCH 16
#define NPIX (W*H)
#define NMAP (BATCH*NPIX)
#define EPSF 1e-4f
#define NT 512

#define NANF __int_as_float(0x7fffffff)

__device__ double g_acc;

// ---- smem layout (floats) ----
// gray 58x58 s60 @0 (3480) ; sga 56x56 s56 @3480 (3136, BORDER only) ; go 44x44 s44 @6616 (1936)
// A @8552 (3520): hs5/vs5 (2112) -> h7x/h7n (2x1760) -> h7s (2x1216)
// B @12072 (5376): hm/vm (2x2688) -> h17 (2x1536)
// C @17448 (4608): pm (2x2304) -> m7 (2x1520)
#define OFF_GRAY 0
#define OFF_SGA  3480
#define OFF_GO   6616
#define OFF_A    8552
#define OFF_B    12072
#define OFF_C    17448
#define SMEM_FLOATS 22056
#define SMEM_BYTES (SMEM_FLOATS * 4)

__global__ void k_zero() { g_acc = 0.0; }

template<int DIR, bool BORDER>
__device__ __forceinline__ void pipe(float* S, int X0, int Y0, int tid,
                                     int mode, float* vsave, double& acc)
{
    float gmv[4], gnv[4];

    // ======== P1 (BORDER only): sga (56x56) |grad|, NaN outside ========
    if (BORDER) {
        #pragma unroll
        for (int idx = tid; idx < 784; idx += NT) {
            int r = idx / 14, g4 = (idx - r * 14) * 4;
            const float* p = S + OFF_GRAY + r * 60 + g4;
            float4 a = *(const float4*)p;
            float n0, n1, n2, n3;
            if (DIR == 0) {
                float e = p[4];
                n0 = a.y; n1 = a.z; n2 = a.w; n3 = e;
            } else {
                float4 bb = *(const float4*)(p + 60);
                n0 = bb.x; n1 = bb.y; n2 = bb.z; n3 = bb.w;
            }
            float4 o;
            o.x = fabsf(a.x - n0); o.y = fabsf(a.y - n1);
            o.z = fabsf(a.z - n2); o.w = fabsf(a.w - n3);
            int gy = Y0 - 12 + r, gxb = X0 - 12 + g4;
            bool iny = (unsigned)gy < (unsigned)H;
            if (!(iny && (unsigned)(gxb + 0) < (unsigned)W)) o.x = NANF;
            if (!(iny && (unsigned)(gxb + 1) < (unsigned)W)) o.y = NANF;
            if (!(iny && (unsigned)(gxb + 2) < (unsigned)W)) o.z = NANF;
            if (!(iny && (unsigned)(gxb + 3) < (unsigned)W)) o.w = NANF;
            *(float4*)(S + OFF_SGA + r * 56 + g4) = o;
        }
        __syncthreads();
    }

    // ======== P2: first pool pass (hm/vm) + telescoped hs5/vs5 ========
    #pragma unroll
    for (int idx = tid; idx < 1200; idx += NT) {
        if (idx < 672) {
            if (BORDER) {
                // R14 path: horizontal 9-tap on sga -> hm[56][48]
                int r = idx / 12, g4 = (idx - r * 12) * 4;
                const float* p = S + OFF_SGA + r * 56 + g4;
                float4 A = *(const float4*)p;
                float4 Bv = *(const float4*)(p + 4);
                float4 Cv = *(const float4*)(p + 8);
                float t0=A.x,t1=A.y,t2=A.z,t3=A.w,t4=Bv.x,t5=Bv.y,t6=Bv.z,t7=Bv.w,t8=Cv.x,t9=Cv.y,t10=Cv.z,t11=Cv.w;
                float cx = fmaxf(fmaxf(fmaxf(t3,t4),fmaxf(t5,t6)),fmaxf(t7,t8));
                float cn = fminf(fminf(fminf(t3,t4),fminf(t5,t6)),fminf(t7,t8));
                float4 ox, on;
                ox.x = fmaxf(fmaxf(fmaxf(cx,t0),t1),t2);
                ox.y = fmaxf(fmaxf(fmaxf(cx,t1),t2),t9);
                ox.z = fmaxf(fmaxf(fmaxf(cx,t2),t9),t10);
                ox.w = fmaxf(fmaxf(fmaxf(cx,t9),t10),t11);
                on.x = fminf(fminf(fminf(cn,t0),t1),t2);
                on.y = fminf(fminf(fminf(cn,t1),t2),t9);
                on.z = fminf(fminf(fminf(cn,t2),t9),t10);
                on.w = fminf(fminf(fminf(cn,t9),t10),t11);
                *(float4*)(S + OFF_B + r * 48 + g4) = ox;
                *(float4*)(S + OFF_B + 2688 + r * 48 + g4) = on;
            } else if (DIR == 0) {
                // interior, dir0: inline grad, horizontal 9-tap -> hm[56][48]
                int r = idx / 12, g4 = (idx - r * 12) * 4;
                const float* p = S + OFF_GRAY + r * 60 + g4;
                float4 A = *(const float4*)p;
                float4 Bv = *(const float4*)(p + 4);
                float4 Cv = *(const float4*)(p + 8);
                float e = p[12];
                float g0=A.x,g1=A.y,g2=A.z,g3=A.w,g4v=Bv.x,g5=Bv.y,g6=Bv.z,g7=Bv.w,g8=Cv.x,g9=Cv.y,g10=Cv.z,g11=Cv.w,g12=e;
                float t0=fabsf(g0-g1),t1=fabsf(g1-g2),t2=fabsf(g2-g3),t3=fabsf(g3-g4v);
                float t4=fabsf(g4v-g5),t5=fabsf(g5-g6),t6=fabsf(g6-g7),t7=fabsf(g7-g8);
                float t8=fabsf(g8-g9),t9=fabsf(g9-g10),t10=fabsf(g10-g11),t11=fabsf(g11-g12);
                float cx = fmaxf(fmaxf(fmaxf(t3,t4),fmaxf(t5,t6)),fmaxf(t7,t8));
                float cn = fminf(fminf(fminf(t3,t4),fminf(t5,t6)),fminf(t7,t8));
                float4 ox, on;
                ox.x = fmaxf(fmaxf(fmaxf(cx,t0),t1),t2);
                ox.y = fmaxf(fmaxf(fmaxf(cx,t1),t2),t9);
                ox.z = fmaxf(fmaxf(fmaxf(cx,t2),t9),t10);
                ox.w = fmaxf(fmaxf(fmaxf(cx,t9),t10),t11);
                on.x = fminf(fminf(fminf(cn,t0),t1),t2);
                on.y = fminf(fminf(fminf(cn,t1),t2),t9);
                on.z = fminf(fminf(fminf(cn,t2),t9),t10);
                on.w = fminf(fminf(fminf(cn,t9),t10),t11);
                *(float4*)(S + OFF_B + r * 48 + g4) = ox;
                *(float4*)(S + OFF_B + 2688 + r * 48 + g4) = on;
            } else {
                // interior, dir1: inline grad, VERTICAL 9-tap first -> vm[48][56]
                int rg = idx / 56, u = idx - rg * 56;   // u 0..55 gray col
                int r4 = rg * 4;
                float g[13];
                #pragma unroll
                for (int q = 0; q < 13; ++q) g[q] = S[OFF_GRAY + (r4 + q) * 60 + u];
                float t[12];
                #pragma unroll
                for (int q = 0; q < 12; ++q) t[q] = fabsf(g[q] - g[q + 1]);
                float cx = fmaxf(fmaxf(fmaxf(t[3],t[4]),fmaxf(t[5],t[6])),fmaxf(t[7],t[8]));
                float cn = fminf(fminf(fminf(t[3],t[4]),fminf(t[5],t[6])),fminf(t[7],t[8]));
                S[OFF_B + (r4 + 0) * 56 + u] = fmaxf(fmaxf(fmaxf(cx,t[0]),t[1]),t[2]);
                S[OFF_B + (r4 + 1) * 56 + u] = fmaxf(fmaxf(fmaxf(cx,t[1]),t[2]),t[9]);
                S[OFF_B + (r4 + 2) * 56 + u] = fmaxf(fmaxf(fmaxf(cx,t[2]),t[9]),t[10]);
                S[OFF_B + (r4 + 3) * 56 + u] = fmaxf(fmaxf(fmaxf(cx,t[9]),t[10]),t[11]);
                S[OFF_B + 2688 + (r4 + 0) * 56 + u] = fminf(fminf(fminf(cn,t[0]),t[1]),t[2]);
                S[OFF_B + 2688 + (r4 + 1) * 56 + u] = fminf(fminf(fminf(cn,t[1]),t[2]),t[9]);
                S[OFF_B + 2688 + (r4 + 2) * 56 + u] = fminf(fminf(fminf(cn,t[2]),t[9]),t[10]);
                S[OFF_B + 2688 + (r4 + 3) * 56 + u] = fminf(fminf(fminf(cn,t[9]),t[10]),t[11]);
            }
        } else {
            int k = idx - 672;    // 528 items
            if (DIR == 0) {
                int r = k / 11, c4 = (k - r * 11) * 4;
                float4 o;
                if (!BORDER) {
                    const float* p = S + OFF_GRAY + (r + 4) * 60 + c4;
                    float4 A = *(const float4*)(p + 4);
                    float4 Bv = *(const float4*)(p + 8);
                    float e = p[12];
                    o = make_float4(A.x - Bv.y, A.y - Bv.z, A.z - Bv.w, A.w - e);
                } else {
                    float v[4];
                    #pragma unroll
                    for (int j = 0; j < 4; ++j) {
                        int acol = c4 + 4 + j;
                        if (X0 == 0) acol = max(acol, 12);
                        float av = S[OFF_GRAY + (r + 4) * 60 + acol];
                        float bv = S[OFF_GRAY + (r + 4) * 60 + c4 + 9 + j];
                        v[j] = av - bv;
                    }
                    o = make_float4(v[0], v[1], v[2], v[3]);
                }
                *(float4*)(S + OFF_A + r * 44 + c4) = o;
            } else {
                int r = k / 12, c4 = (k - r * 12) * 4;
                int arow = r + 4;
                if (BORDER && Y0 == 0) arow = max(arow, 12);
                float4 T = *(const float4*)(S + OFF_GRAY + arow * 60 + c4 + 4);
                float4 Bo = *(const float4*)(S + OFF_GRAY + (r + 9) * 60 + c4 + 4);
                *(float4*)(S + OFF_A + r * 48 + c4) =
                    make_float4(T.x - Bo.x, T.y - Bo.y, T.z - Bo.z, T.w - Bo.w);
            }
        }
    }
    __syncthreads();

    // ======== P3: pm (48x48) + go (44x44) ========
    #pragma unroll
    for (int idx = tid; idx < 1060; idx += NT) {
        if (idx < 576) {
            if (BORDER || DIR == 0) {
                // vertical 9-tap on hm[56][48]
                int rg = idx / 48, c = idx - rg * 48;
                int r4 = rg * 4;
                {
                    float t[12];
                    #pragma unroll
                    for (int q = 0; q < 12; ++q) t[q] = S[OFF_B + (r4 + q) * 48 + c];
                    float cx = fmaxf(fmaxf(fmaxf(t[3],t[4]),fmaxf(t[5],t[6])),fmaxf(t[7],t[8]));
                    float o0 = fmaxf(fmaxf(fmaxf(cx,t[0]),t[1]),t[2]);
                    float o1 = fmaxf(fmaxf(fmaxf(cx,t[1]),t[2]),t[9]);
                    float o2 = fmaxf(fmaxf(fmaxf(cx,t[2]),t[9]),t[10]);
                    float o3 = fmaxf(fmaxf(fmaxf(cx,t[9]),t[10]),t[11]);
                    if (BORDER) {
                        int gx = X0 - 8 + c;
                        bool inx = (unsigned)gx < (unsigned)W;
                        int gyb = Y0 - 8 + r4;
                        if (!(inx && (unsigned)(gyb+0)<(unsigned)H)) o0 = 0.f;
                        if (!(inx && (unsigned)(gyb+1)<(unsigned)H)) o1 = 0.f;
                        if (!(inx && (unsigned)(gyb+2)<(unsigned)H)) o2 = 0.f;
                        if (!(inx && (unsigned)(gyb+3)<(unsigned)H)) o3 = 0.f;
                    }
                    S[OFF_C + (r4 + 0) * 48 + c] = o0;
                    S[OFF_C + (r4 + 1) * 48 + c] = o1;
                    S[OFF_C + (r4 + 2) * 48 + c] = o2;
                    S[OFF_C + (r4 + 3) * 48 + c] = o3;
                }
                {
                    float t[12];
                    #pragma unroll
                    for (int q = 0; q < 12; ++q) t[q] = S[OFF_B + 2688 + (r4 + q) * 48 + c];
                    float cn = fminf(fminf(fminf(t[3],t[4]),fminf(t[5],t[6])),fminf(t[7],t[8]));
                    float o0 = fminf(fminf(fminf(cn,t[0]),t[1]),t[2]);
                    float o1 = fminf(fminf(fminf(cn,t[1]),t[2]),t[9]);
                    float o2 = fminf(fminf(fminf(cn,t[2]),t[9]),t[10]);
                    float o3 = fminf(fminf(fminf(cn,t[9]),t[10]),t[11]);
                    if (BORDER) {
                        int gx = X0 - 8 + c;
                        bool inx = (unsigned)gx < (unsigned)W;
                        int gyb = Y0 - 8 + r4;
                        if (!(inx && (unsigned)(gyb+0)<(unsigned)H)) o0 = 0.f;
                        if (!(inx && (unsigned)(gyb+1)<(unsigned)H)) o1 = 0.f;
                        if (!(inx && (unsigned)(gyb+2)<(unsigned)H)) o2 = 0.f;
                        if (!(inx && (unsigned)(gyb+3)<(unsigned)H)) o3 = 0.f;
                    }
                    S[OFF_C + 2304 + (r4 + 0) * 48 + c] = o0;
                    S[OFF_C + 2304 + (r4 + 1) * 48 + c] = o1;
                    S[OFF_C + 2304 + (r4 + 2) * 48 + c] = o2;
                    S[OFF_C + 2304 + (r4 + 3) * 48 + c] = o3;
                }
            } else {
                // interior dir1: horizontal 9-tap on vm[48][56] (float4 reads)
                int r = idx / 12, g4 = (idx - r * 12) * 4;
                #pragma unroll
                for (int arr = 0; arr < 2; ++arr) {
                    const float* p = S + OFF_B + arr * 2688 + r * 56 + g4;
                    float4 A = *(const float4*)p;
                    float4 Bv = *(const float4*)(p + 4);
                    float4 Cv = *(const float4*)(p + 8);
                    float t0=A.x,t1=A.y,t2=A.z,t3=A.w,t4=Bv.x,t5=Bv.y,t6=Bv.z,t7=Bv.w,t8=Cv.x,t9=Cv.y,t10=Cv.z,t11=Cv.w;
                    float4 o;
                    if (arr == 0) {
                        float cx = fmaxf(fmaxf(fmaxf(t3,t4),fmaxf(t5,t6)),fmaxf(t7,t8));
                        o.x = fmaxf(fmaxf(fmaxf(cx,t0),t1),t2);
                        o.y = fmaxf(fmaxf(fmaxf(cx,t1),t2),t9);
                        o.z = fmaxf(fmaxf(fmaxf(cx,t2),t9),t10);
                        o.w = fmaxf(fmaxf(fmaxf(cx,t9),t10),t11);
                    } else {
                        float cn = fminf(fminf(fminf(t3,t4),fminf(t5,t6)),fminf(t7,t8));
                        o.x = fminf(fminf(fminf(cn,t0),t1),t2);
                        o.y = fminf(fminf(fminf(cn,t1),t2),t9);
                        o.z = fminf(fminf(fminf(cn,t2),t9),t10);
                        o.w = fminf(fminf(fminf(cn,t9),t10),t11);
                    }
                    *(float4*)(S + OFF_C + arr * 2304 + r * 48 + g4) = o;
                }
            }
        } else {
            int k = idx - 576;    // 484 items -> go
            if (DIR == 0) {
                int rg = k / 44, c = k - rg * 44;
                int r4 = rg * 4;
                float t[8];
                #pragma unroll
                for (int q = 0; q < 8; ++q) t[q] = S[OFF_A + (r4 + q) * 44 + c];
                float s0 = t[0] + t[1] + t[2] + t[3] + t[4];
                float s1 = s0 - t[0] + t[5];
                float s2 = s1 - t[1] + t[6];
                float s3 = s2 - t[2] + t[7];
                float ss[4] = { s0, s1, s2, s3 };
                #pragma unroll
                for (int j = 0; j < 4; ++j) {
                    float v;
                    if (!BORDER) {
                        v = fabsf(ss[j] * 0.04f);
                    } else {
                        int gx = X0 - 6 + c, gy = Y0 - 6 + r4 + j;
                        if ((unsigned)gx < (unsigned)W && (unsigned)gy < (unsigned)H) {
                            float cntx = (float)(min(gx + 2, W - 1) - max(gx - 2, 0) + 1);
                            float cnty = (float)(min(gy + 2, H - 1) - max(gy - 2, 0) + 1);
                            v = fabsf(__fdividef(ss[j], cntx * cnty));
                        } else v = NANF;
                    }
                    S[OFF_GO + (r4 + j) * 44 + c] = v;
                }
            } else {
                int r = k / 11, c4 = (k - r * 11) * 4;
                float4 A = *(const float4*)(S + OFF_A + r * 48 + c4);
                float4 Bv = *(const float4*)(S + OFF_A + r * 48 + c4 + 4);
                float t0=A.x,t1=A.y,t2=A.z,t3=A.w,t4=Bv.x,t5=Bv.y,t6=Bv.z,t7=Bv.w;
                float s0 = t0 + t1 + t2 + t3 + t4;
                float s1 = s0 - t0 + t5;
                float s2 = s1 - t1 + t6;
                float s3 = s2 - t2 + t7;
                float ss[4] = { s0, s1, s2, s3 };
                float4 o;
                float* op = &o.x;
                #pragma unroll
                for (int j = 0; j < 4; ++j) {
                    float v;
                    if (!BORDER) {
                        v = fabsf(ss[j] * 0.04f);
                    } else {
                        int gx = X0 - 6 + c4 + j, gy = Y0 - 6 + r;
                        if ((unsigned)gx < (unsigned)W && (unsigned)gy < (unsigned)H) {
                            float cntx = (float)(min(gx + 2, W - 1) - max(gx - 2, 0) + 1);
                            float cnty = (float)(min(gy + 2, H - 1) - max(gy - 2, 0) + 1);
                            v = fabsf(__fdividef(ss[j], cntx * cnty));
                        } else v = NANF;
                    }
                    op[j] = v;
                }
                *(float4*)(S + OFF_GO + r * 44 + c4) = o;
            }
        }
    }
    __syncthreads();

    // ======== P4: h17 (48x32) + h7 (44x38) ========
    #pragma unroll
    for (int idx = tid; idx < 824; idx += NT) {
        if (idx < 384) {
            int r = idx / 8, g4 = (idx & 7) * 4;
            #pragma unroll
            for (int arr = 0; arr < 2; ++arr) {
                const float* p = S + OFF_C + arr * 2304 + r * 48 + g4;
                float t[20];
                #pragma unroll
                for (int q = 0; q < 5; ++q) {
                    float4 v = *(const float4*)(p + q * 4);
                    t[q*4] = v.x; t[q*4+1] = v.y; t[q*4+2] = v.z; t[q*4+3] = v.w;
                }
                float s0 = 0.f;
                #pragma unroll
                for (int q = 0; q < 17; ++q) s0 += t[q];
                float s1 = s0 - t[0] + t[17];
                float s2 = s1 - t[1] + t[18];
                float s3 = s2 - t[2] + t[19];
                *(float4*)(S + OFF_B + arr * 1536 + r * 32 + g4) = make_float4(s0, s1, s2, s3);
            }
        } else {
            int k = idx - 384;     // 440 items
            int r = k / 10, g = k - r * 10;
            if (g < 9) {
                int g4 = g * 4;
                const float* p = S + OFF_GO + r * 44 + g4;
                float4 A = *(const float4*)p;
                float4 Bv = *(const float4*)(p + 4);
                float4 Cv = *(const float4*)(p + 8);
                float t0=A.x,t1=A.y,t2=A.z,t3=A.w,t4=Bv.x,t5=Bv.y,t6=Bv.z,t7=Bv.w,t8=Cv.x,t9=Cv.y;
                float cx = fmaxf(fmaxf(t3,t4),fmaxf(t5,t6));
                float cn = fminf(fminf(t3,t4),fminf(t5,t6));
                float4 ox, on;
                ox.x = fmaxf(fmaxf(fmaxf(cx,t0),t1),t2);
                ox.y = fmaxf(fmaxf(fmaxf(cx,t1),t2),t7);
                ox.z = fmaxf(fmaxf(fmaxf(cx,t2),t7),t8);
                ox.w = fmaxf(fmaxf(fmaxf(cx,t7),t8),t9);
                on.x = fminf(fminf(fminf(cn,t0),t1),t2);
                on.y = fminf(fminf(fminf(cn,t1),t2),t7);
                on.z = fminf(fminf(fminf(cn,t2),t7),t8);
                on.w = fminf(fminf(fminf(cn,t7),t8),t9);
                *(float4*)(S + OFF_A + r * 40 + g4) = ox;
                *(float4*)(S + OFF_A + 1760 + r * 40 + g4) = on;
            } else {
                const float* p = S + OFF_GO + r * 44 + 36;
                float4 A = *(const float4*)p;
                float4 Bv = *(const float4*)(p + 4);
                float t0=A.x,t1=A.y,t2=A.z,t3=A.w,t4=Bv.x,t5=Bv.y,t6=Bv.z,t7=Bv.w;
                float c6x = fmaxf(fmaxf(t1,t2),fmaxf(fmaxf(t3,t4),fmaxf(t5,t6)));
                float c6n = fminf(fminf(t1,t2),fminf(fminf(t3,t4),fminf(t5,t6)));
                S[OFF_A + r * 40 + 36] = fmaxf(c6x, t0);
                S[OFF_A + r * 40 + 37] = fmaxf(c6x, t7);
                S[OFF_A + 1760 + r * 40 + 36] = fminf(c6n, t0);
                S[OFF_A + 1760 + r * 40 + 37] = fminf(c6n, t7);
            }
        }
    }
    __syncthreads();

    // ======== P5: v17 -> regs on tids 0-255  ||  m7 on tids 256-511 ========
    if (tid < 256) {
        int rg = tid >> 5, c = tid & 31;
        int r0 = rg * 4;
        float inv[4];
        if (!BORDER) {
            #pragma unroll
            for (int j = 0; j < 4; ++j) inv[j] = 1.f / 289.f;
        } else {
            int gx = X0 + c;
            float cntx = (float)(min(gx + 8, W - 1) - max(gx - 8, 0) + 1);
            #pragma unroll
            for (int j = 0; j < 4; ++j) {
                int gy = Y0 + r0 + j;
                float cnty = (float)(min(gy + 8, H - 1) - max(gy - 8, 0) + 1);
                inv[j] = __fdividef(1.f, cntx * cnty);
            }
        }
        {
            float t[20];
            #pragma unroll
            for (int q = 0; q < 20; ++q) t[q] = S[OFF_B + (r0 + q) * 32 + c];
            float s0 = 0.f;
            #pragma unroll
            for (int q = 0; q < 17; ++q) s0 += t[q];
            float s1 = s0 - t[0] + t[17];
            float s2 = s1 - t[1] + t[18];
            float s3 = s2 - t[2] + t[19];
            gmv[0] = s0 * inv[0]; gmv[1] = s1 * inv[1];
            gmv[2] = s2 * inv[2]; gmv[3] = s3 * inv[3];
        }
        {
            float t[20];
            #pragma unroll
            for (int q = 0; q < 20; ++q) t[q] = S[OFF_B + 1536 + (r0 + q) * 32 + c];
            float s0 = 0.f;
            #pragma unroll
            for (int q = 0; q < 17; ++q) s0 += t[q];
            float s1 = s0 - t[0] + t[17];
            float s2 = s1 - t[1] + t[18];
            float s3 = s2 - t[2] + t[19];
            gnv[0] = s0 * inv[0]; gnv[1] = s1 * inv[1];
            gnv[2] = s2 * inv[2]; gnv[3] = s3 * inv[3];
        }
    } else {
        #pragma unroll
        for (int k = tid - 256; k < 380; k += 256) {
            int rg = k / 38, c = k - rg * 38;
            int r0 = min(rg * 4, 34);
            #pragma unroll
            for (int arr = 0; arr < 2; ++arr) {
                float t[10];
                #pragma unroll
                for (int q = 0; q < 10; ++q) t[q] = S[OFF_A + arr * 1760 + (r0 + q) * 40 + c];
                float o0, o1, o2, o3;
                if (arr == 0) {
                    float cx = fmaxf(fmaxf(t[3],t[4]),fmaxf(t[5],t[6]));
                    o0 = fmaxf(fmaxf(fmaxf(cx,t[0]),t[1]),t[2]);
                    o1 = fmaxf(fmaxf(fmaxf(cx,t[1]),t[2]),t[7]);
                    o2 = fmaxf(fmaxf(fmaxf(cx,t[2]),t[7]),t[8]);
                    o3 = fmaxf(fmaxf(fmaxf(cx,t[7]),t[8]),t[9]);
                } else {
                    float cn = fminf(fminf(t[3],t[4]),fminf(t[5],t[6]));
                    o0 = fminf(fminf(fminf(cn,t[0]),t[1]),t[2]);
                    o1 = fminf(fminf(fminf(cn,t[1]),t[2]),t[7]);
                    o2 = fminf(fminf(fminf(cn,t[2]),t[7]),t[8]);
                    o3 = fminf(fminf(fminf(cn,t[7]),t[8]),t[9]);
                }
                if (BORDER) {
                    int gx = X0 - 3 + c;
                    bool inx = (unsigned)gx < (unsigned)W;
                    int gyb = Y0 - 3 + r0;
                    if (!(inx && (unsigned)(gyb+0)<(unsigned)H)) o0 = 0.f;
                    if (!(inx && (unsigned)(gyb+1)<(unsigned)H)) o1 = 0.f;
                    if (!(inx && (unsigned)(gyb+2)<(unsigned)H)) o2 = 0.f;
                    if (!(inx && (unsigned)(gyb+3)<(unsigned)H)) o3 = 0.f;
                }
                S[OFF_C + arr * 1520 + (r0 + 0) * 40 + c] = o0;
                S[OFF_C + arr * 1520 + (r0 + 1) * 40 + c] = o1;
                S[OFF_C + arr * 1520 + (r0 + 2) * 40 + c] = o2;
                S[OFF_C + arr * 1520 + (r0 + 3) * 40 + c] = o3;
            }
        }
    }
    __syncthreads();

    // ======== P6: h7s (38x32) ========
    #pragma unroll
    for (int idx = tid; idx < 304; idx += NT) {
        int r = idx / 8, g4 = (idx & 7) * 4;
        #pragma unroll
        for (int arr = 0; arr < 2; ++arr) {
            const float* p = S + OFF_C + arr * 1520 + r * 40 + g4;
            float4 A = *(const float4*)p;
            float4 Bv = *(const float4*)(p + 4);
            float4 Cv = *(const float4*)(p + 8);
            float t0=A.x,t1=A.y,t2=A.z,t3=A.w,t4=Bv.x,t5=Bv.y,t6=Bv.z,t7=Bv.w,t8=Cv.x,t9=Cv.y;
            float s0 = t0+t1+t2+t3+t4+t5+t6;
            float s1 = s0 - t0 + t7;
            float s2 = s1 - t1 + t8;
            float s3 = s2 - t2 + t9;
            *(float4*)(S + OFF_A + arr * 1216 + r * 32 + g4) = make_float4(s0, s1, s2, s3);
        }
    }
    __syncthreads();

    // ======== P7: final (32x32) ========
    if (tid < 256) {
        int rg = tid >> 5, c = tid & 31;
        int r0 = rg * 4;
        float sA[4], sD[4];
        {
            float t[10];
            #pragma unroll
            for (int q = 0; q < 10; ++q) t[q] = S[OFF_A + (r0 + q) * 32 + c];
            sA[0] = t[0]+t[1]+t[2]+t[3]+t[4]+t[5]+t[6];
            sA[1] = sA[0] - t[0] + t[7];
            sA[2] = sA[1] - t[1] + t[8];
            sA[3] = sA[2] - t[2] + t[9];
        }
        {
            float t[10];
            #pragma unroll
            for (int q = 0; q < 10; ++q) t[q] = S[OFF_A + 1216 + (r0 + q) * 32 + c];
            sD[0] = t[0]+t[1]+t[2]+t[3]+t[4]+t[5]+t[6];
            sD[1] = sD[0] - t[0] + t[7];
            sD[2] = sD[1] - t[1] + t[8];
            sD[3] = sD[2] - t[2] + t[9];
        }
        #pragma unroll
        for (int j = 0; j < 4; ++j) {
            float inv;
            if (!BORDER) {
                inv = 1.f / 49.f;
            } else {
                int gx = X0 + c, gy = Y0 + r0 + j;
                float cntx = (float)(min(gx + 3, W - 1) - max(gx - 3, 0) + 1);
                float cnty = (float)(min(gy + 3, H - 1) - max(gy - 3, 0) + 1);
                inv = __fdividef(1.f, cntx * cnty);
            }
            float pmax = sA[j] * inv, pmin = sD[j] * inv;
            float go = S[OFF_GO + (r0 + j + 6) * 44 + c + 6];
            float ga;
            if (BORDER) {
                ga = S[OFF_SGA + (r0 + j + 12) * 56 + c + 12];
            } else {
                int u = c + 12, rho = r0 + j + 12;
                float gc = S[OFF_GRAY + rho * 60 + u];
                float gn_ = (DIR == 0) ? S[OFF_GRAY + rho * 60 + u + 1]
                                       : S[OFF_GRAY + (rho + 1) * 60 + u];
                ga = fabsf(gc - gn_);
            }
            float gn = __fdividef(go - pmin, fabsf(pmax - pmin) + EPSF);
            float gn1 = __fdividef(ga - gnv[j], fabsf(gmv[j] - gnv[j]) + EPSF);
            float val = (gn + 0.01f) * gn1;
            if (mode == 0) {
                vsave[j] = val;
            } else {
                float rv = vsave[j];
                acc += (double)(rv * expf(-10.f * (rv + val)));
            }
        }
    }
    __syncthreads();
}

template<bool BORDER>
__device__ __forceinline__ void run(float* S, int X0, int Y0, int b, int tid, double& acc,
                                    const float* __restrict__ img0,
                                    const float* __restrict__ img1)
{
    float vsx[4], vsy[4];
    #pragma unroll
    for (int img = 0; img < 2; ++img) {
        const float* __restrict__ ip = (img == 0 ? img0 : img1) + (size_t)b * 3 * NPIX;
        if (!BORDER) {
            #pragma unroll
            for (int idx = tid; idx < 870; idx += NT) {
                int r = idx / 15, c4 = (idx - r * 15) * 4;
                size_t off = (size_t)(Y0 - 12 + r) * W + (X0 - 12 + c4);
                float4 rv = *(const float4*)(ip + off);
                float4 gv = *(const float4*)(ip + NPIX + off);
                float4 bv = *(const float4*)(ip + 2 * NPIX + off);
                float4 o;
                o.x = 0.299f * rv.x + 0.587f * gv.x + 0.114f * bv.x;
                o.y = 0.299f * rv.y + 0.587f * gv.y + 0.114f * bv.y;
                o.z = 0.299f * rv.z + 0.587f * gv.z + 0.114f * bv.z;
                o.w = 0.299f * rv.w + 0.587f * gv.w + 0.114f * bv.w;
                *(float4*)(S + OFF_GRAY + r * 60 + c4) = o;
            }
        } else {
            for (int idx = tid; idx < 3364; idx += NT) {
                int r = idx / 58, c = idx - r * 58;
                int gy = Y0 - 12 + r, gx = X0 - 12 + c;
                float v = 0.f;
                if ((unsigned)gx < (unsigned)W && (unsigned)gy < (unsigned)H) {
                    size_t off = (size_t)gy * W + gx;
                    v = 0.299f * __ldg(ip + off)
                      + 0.587f * __ldg(ip + NPIX + off)
                      + 0.114f * __ldg(ip + 2 * NPIX + off);
                }
                S[OFF_GRAY + r * 60 + c] = v;
            }
        }
        __syncthreads();
        pipe<0, BORDER>(S, X0, Y0, tid, img, vsx, acc);
        pipe<1, BORDER>(S, X0, Y0, tid, img, vsy, acc);
        __syncthreads();   // protect gray tile before next img overwrites
    }
}

__global__ __launch_bounds__(NT, 2)
void k_mega(const float* __restrict__ img0, const float* __restrict__ img1) {
    extern __shared__ float S[];
    __shared__ double sred[NT / 32];

    const int b = blockIdx.z;
    const int X0 = blockIdx.x * 32, Y0 = blockIdx.y * 32;
    const int tid = threadIdx.x;

    double acc = 0.0;
    bool border = (blockIdx.x == 0) | (blockIdx.x == 15) | (blockIdx.y == 0) | (blockIdx.y == 15);
    if (border) run<true>(S, X0, Y0, b, tid, acc, img0, img1);
    else        run<false>(S, X0, Y0, b, tid, acc, img0, img1);

    int tx = tid & 31, ty = tid >> 5;
    #pragma unroll
    for (int off = 16; off; off >>= 1) acc += __shfl_down_sync(0xffffffffu, acc, off);
    if (tx == 0) sred[ty] = acc;
    __syncthreads();
    if (ty == 0 && tx < NT / 32) {
        double w = sred[tx];
        #pragma unroll
        for (int off = (NT / 64); off; off >>= 1) w += __shfl_down_sync(0xffffffffu, w, off);
        if (tx == 0) atomicAdd(&g_acc, w);
    }
}

__global__ void k_out(float* __restrict__ out) {
    out[0] = (float)(g_acc / (double)NMAP);
}

extern "C" void kernel_launch(void* const* d_in, const int* in_sizes, int n_in,
                              void* d_out, int out_size) {
    const float* R_low = (const float*)d_in[0];
    const float* low = (const float*)d_in[1];
    float* out = (float*)d_out;

    cudaFuncSetAttribute(k_mega, cudaFuncAttributeMaxDynamicSharedMemorySize, SMEM_BYTES);

    k_zero<<<1, 1>>>();
    dim3 grd(16, 16, 16);
    k_mega<<<grd, NT, SMEM_BYTES>>>(R_low, low);
    k_out<<<1, 1>>>(out);
}

// round 16
// speedup vs baseline: 1.1611x; 1.0028x over previous
#include <cuda_runtime.h>
#include <math.h>

#define W 512
#define H 512
#define BATCH 16
#define NPIX (W*H)
#define NMAP (BATCH*NPIX)
#define EPSF 1e-4f
#define NT 512

#define NANF __int_as_float(0x7fffffff)

__device__ double g_acc;   // zero-initialized; k_out resets after each read

// ---- smem layout (floats) ----
// gray 58x58 s60 @0 (3480) ; sga 56x56 s56 @3480 (3136, BORDER only) ; go 44x44 s44 @6616 (1936)
// A @8552 (3520): h7x/h7n (2x1760) -> h7s (2x1216)
// B @12072 (5376): hm/vm (2x2688) -> h17 (2x1536)
// C @17448 (4608): pm (2x2304) -> m7 (2x1520)
// D @22056 (2112): hs5 (48x44) / vs5 (44x48)   [dedicated, never aliased]
#define OFF_GRAY 0
#define OFF_SGA  3480
#define OFF_GO   6616
#define OFF_A    8552
#define OFF_B    12072
#define OFF_C    17448
#define OFF_D    22056
#define SMEM_FLOATS 24168
#define SMEM_BYTES (SMEM_FLOATS * 4)

template<int DIR, bool BORDER>
__device__ __forceinline__ void pipe(float* S, int X0, int Y0, int tid,
                                     int mode, float* vsave, double& acc)
{
    float gmv[4], gnv[4];

    // ======== P1 (BORDER only): sga (56x56) |grad|, NaN outside ========
    if (BORDER) {
        #pragma unroll
        for (int idx = tid; idx < 784; idx += NT) {
            int r = idx / 14, g4 = (idx - r * 14) * 4;
            const float* p = S + OFF_GRAY + r * 60 + g4;
            float4 a = *(const float4*)p;
            float n0, n1, n2, n3;
            if (DIR == 0) {
                float e = p[4];
                n0 = a.y; n1 = a.z; n2 = a.w; n3 = e;
            } else {
                float4 bb = *(const float4*)(p + 60);
                n0 = bb.x; n1 = bb.y; n2 = bb.z; n3 = bb.w;
            }
            float4 o;
            o.x = fabsf(a.x - n0); o.y = fabsf(a.y - n1);
            o.z = fabsf(a.z - n2); o.w = fabsf(a.w - n3);
            int gy = Y0 - 12 + r, gxb = X0 - 12 + g4;
            bool iny = (unsigned)gy < (unsigned)H;
            if (!(iny && (unsigned)(gxb + 0) < (unsigned)W)) o.x = NANF;
            if (!(iny && (unsigned)(gxb + 1) < (unsigned)W)) o.y = NANF;
            if (!(iny && (unsigned)(gxb + 2) < (unsigned)W)) o.z = NANF;
            if (!(iny && (unsigned)(gxb + 3) < (unsigned)W)) o.w = NANF;
            *(float4*)(S + OFF_SGA + r * 56 + g4) = o;
        }
        __syncthreads();
    }

    // ======== P2: first pool pass (hm/vm) + telescoped hs5/vs5 (region D) ========
    #pragma unroll
    for (int idx = tid; idx < 1200; idx += NT) {
        if (idx < 672) {
            if (BORDER) {
                int r = idx / 12, g4 = (idx - r * 12) * 4;
                const float* p = S + OFF_SGA + r * 56 + g4;
                float4 A = *(const float4*)p;
                float4 Bv = *(const float4*)(p + 4);
                float4 Cv = *(const float4*)(p + 8);
                float t0=A.x,t1=A.y,t2=A.z,t3=A.w,t4=Bv.x,t5=Bv.y,t6=Bv.z,t7=Bv.w,t8=Cv.x,t9=Cv.y,t10=Cv.z,t11=Cv.w;
                float cx = fmaxf(fmaxf(fmaxf(t3,t4),fmaxf(t5,t6)),fmaxf(t7,t8));
                float cn = fminf(fminf(fminf(t3,t4),fminf(t5,t6)),fminf(t7,t8));
                float4 ox, on;
                ox.x = fmaxf(fmaxf(fmaxf(cx,t0),t1),t2);
                ox.y = fmaxf(fmaxf(fmaxf(cx,t1),t2),t9);
                ox.z = fmaxf(fmaxf(fmaxf(cx,t2),t9),t10);
                ox.w = fmaxf(fmaxf(fmaxf(cx,t9),t10),t11);
                on.x = fminf(fminf(fminf(cn,t0),t1),t2);
                on.y = fminf(fminf(fminf(cn,t1),t2),t9);
                on.z = fminf(fminf(fminf(cn,t2),t9),t10);
                on.w = fminf(fminf(fminf(cn,t9),t10),t11);
                *(float4*)(S + OFF_B + r * 48 + g4) = ox;
                *(float4*)(S + OFF_B + 2688 + r * 48 + g4) = on;
            } else if (DIR == 0) {
                int r = idx / 12, g4 = (idx - r * 12) * 4;
                const float* p = S + OFF_GRAY + r * 60 + g4;
                float4 A = *(const float4*)p;
                float4 Bv = *(const float4*)(p + 4);
                float4 Cv = *(const float4*)(p + 8);
                float e = p[12];
                float g0=A.x,g1=A.y,g2=A.z,g3=A.w,g4v=Bv.x,g5=Bv.y,g6=Bv.z,g7=Bv.w,g8=Cv.x,g9=Cv.y,g10=Cv.z,g11=Cv.w,g12=e;
                float t0=fabsf(g0-g1),t1=fabsf(g1-g2),t2=fabsf(g2-g3),t3=fabsf(g3-g4v);
                float t4=fabsf(g4v-g5),t5=fabsf(g5-g6),t6=fabsf(g6-g7),t7=fabsf(g7-g8);
                float t8=fabsf(g8-g9),t9=fabsf(g9-g10),t10=fabsf(g10-g11),t11=fabsf(g11-g12);
                float cx = fmaxf(fmaxf(fmaxf(t3,t4),fmaxf(t5,t6)),fmaxf(t7,t8));
                float cn = fminf(fminf(fminf(t3,t4),fminf(t5,t6)),fminf(t7,t8));
                float4 ox, on;
                ox.x = fmaxf(fmaxf(fmaxf(cx,t0),t1),t2);
                ox.y = fmaxf(fmaxf(fmaxf(cx,t1),t2),t9);
                ox.z = fmaxf(fmaxf(fmaxf(cx,t2),t9),t10);
                ox.w = fmaxf(fmaxf(fmaxf(cx,t9),t10),t11);
                on.x = fminf(fminf(fminf(cn,t0),t1),t2);
                on.y = fminf(fminf(fminf(cn,t1),t2),t9);
                on.z = fminf(fminf(fminf(cn,t2),t9),t10);
                on.w = fminf(fminf(fminf(cn,t9),t10),t11);
                *(float4*)(S + OFF_B + r * 48 + g4) = ox;
                *(float4*)(S + OFF_B + 2688 + r * 48 + g4) = on;
            } else {
                int rg = idx / 56, u = idx - rg * 56;
                int r4 = rg * 4;
                float g[13];
                #pragma unroll
                for (int q = 0; q < 13; ++q) g[q] = S[OFF_GRAY + (r4 + q) * 60 + u];
                float t[12];
                #pragma unroll
                for (int q = 0; q < 12; ++q) t[q] = fabsf(g[q] - g[q + 1]);
                float cx = fmaxf(fmaxf(fmaxf(t[3],t[4]),fmaxf(t[5],t[6])),fmaxf(t[7],t[8]));
                float cn = fminf(fminf(fminf(t[3],t[4]),fminf(t[5],t[6])),fminf(t[7],t[8]));
                S[OFF_B + (r4 + 0) * 56 + u] = fmaxf(fmaxf(fmaxf(cx,t[0]),t[1]),t[2]);
                S[OFF_B + (r4 + 1) * 56 + u] = fmaxf(fmaxf(fmaxf(cx,t[1]),t[2]),t[9]);
                S[OFF_B + (r4 + 2) * 56 + u] = fmaxf(fmaxf(fmaxf(cx,t[2]),t[9]),t[10]);
                S[OFF_B + (r4 + 3) * 56 + u] = fmaxf(fmaxf(fmaxf(cx,t[9]),t[10]),t[11]);
                S[OFF_B + 2688 + (r4 + 0) * 56 + u] = fminf(fminf(fminf(cn,t[0]),t[1]),t[2]);
                S[OFF_B + 2688 + (r4 + 1) * 56 + u] = fminf(fminf(fminf(cn,t[1]),t[2]),t[9]);
                S[OFF_B + 2688 + (r4 + 2) * 56 + u] = fminf(fminf(fminf(cn,t[2]),t[9]),t[10]);
                S[OFF_B + 2688 + (r4 + 3) * 56 + u] = fminf(fminf(fminf(cn,t[9]),t[10]),t[11]);
            }
        } else {
            int k = idx - 672;    // 528 items
            if (DIR == 0) {
                int r = k / 11, c4 = (k - r * 11) * 4;
                float4 o;
                if (!BORDER) {
                    const float* p = S + OFF_GRAY + (r + 4) * 60 + c4;
                    float4 A = *(const float4*)(p + 4);
                    float4 Bv = *(const float4*)(p + 8);
                    float e = p[12];
                    o = make_float4(A.x - Bv.y, A.y - Bv.z, A.z - Bv.w, A.w - e);
                } else {
                    float v[4];
                    #pragma unroll
                    for (int j = 0; j < 4; ++j) {
                        int acol = c4 + 4 + j;
                        if (X0 == 0) acol = max(acol, 12);
                        float av = S[OFF_GRAY + (r + 4) * 60 + acol];
                        float bv = S[OFF_GRAY + (r + 4) * 60 + c4 + 9 + j];
                        v[j] = av - bv;
                    }
                    o = make_float4(v[0], v[1], v[2], v[3]);
                }
                *(float4*)(S + OFF_D + r * 44 + c4) = o;
            } else {
                int r = k / 12, c4 = (k - r * 12) * 4;
                int arow = r + 4;
                if (BORDER && Y0 == 0) arow = max(arow, 12);
                float4 T = *(const float4*)(S + OFF_GRAY + arow * 60 + c4 + 4);
                float4 Bo = *(const float4*)(S + OFF_GRAY + (r + 9) * 60 + c4 + 4);
                *(float4*)(S + OFF_D + r * 48 + c4) =
                    make_float4(T.x - Bo.x, T.y - Bo.y, T.z - Bo.z, T.w - Bo.w);
            }
        }
    }
    __syncthreads();

    // ======== P3: pm (48x48) + go (44x44) ========
    #pragma unroll
    for (int idx = tid; idx < 1060; idx += NT) {
        if (idx < 576) {
            if (BORDER || DIR == 0) {
                int rg = idx / 48, c = idx - rg * 48;
                int r4 = rg * 4;
                {
                    float t[12];
                    #pragma unroll
                    for (int q = 0; q < 12; ++q) t[q] = S[OFF_B + (r4 + q) * 48 + c];
                    float cx = fmaxf(fmaxf(fmaxf(t[3],t[4]),fmaxf(t[5],t[6])),fmaxf(t[7],t[8]));
                    float o0 = fmaxf(fmaxf(fmaxf(cx,t[0]),t[1]),t[2]);
                    float o1 = fmaxf(fmaxf(fmaxf(cx,t[1]),t[2]),t[9]);
                    float o2 = fmaxf(fmaxf(fmaxf(cx,t[2]),t[9]),t[10]);
                    float o3 = fmaxf(fmaxf(fmaxf(cx,t[9]),t[10]),t[11]);
                    if (BORDER) {
                        int gx = X0 - 8 + c;
                        bool inx = (unsigned)gx < (unsigned)W;
                        int gyb = Y0 - 8 + r4;
                        if (!(inx && (unsigned)(gyb+0)<(unsigned)H)) o0 = 0.f;
                        if (!(inx && (unsigned)(gyb+1)<(unsigned)H)) o1 = 0.f;
                        if (!(inx && (unsigned)(gyb+2)<(unsigned)H)) o2 = 0.f;
                        if (!(inx && (unsigned)(gyb+3)<(unsigned)H)) o3 = 0.f;
                    }
                    S[OFF_C + (r4 + 0) * 48 + c] = o0;
                    S[OFF_C + (r4 + 1) * 48 + c] = o1;
                    S[OFF_C + (r4 + 2) * 48 + c] = o2;
                    S[OFF_C + (r4 + 3) * 48 + c] = o3;
                }
                {
                    float t[12];
                    #pragma unroll
                    for (int q = 0; q < 12; ++q) t[q] = S[OFF_B + 2688 + (r4 + q) * 48 + c];
                    float cn = fminf(fminf(fminf(t[3],t[4]),fminf(t[5],t[6])),fminf(t[7],t[8]));
                    float o0 = fminf(fminf(fminf(cn,t[0]),t[1]),t[2]);
                    float o1 = fminf(fminf(fminf(cn,t[1]),t[2]),t[9]);
                    float o2 = fminf(fminf(fminf(cn,t[2]),t[9]),t[10]);
                    float o3 = fminf(fminf(fminf(cn,t[9]),t[10]),t[11]);
                    if (BORDER) {
                        int gx = X0 - 8 + c;
                        bool inx = (unsigned)gx < (unsigned)W;
                        int gyb = Y0 - 8 + r4;
                        if (!(inx && (unsigned)(gyb+0)<(unsigned)H)) o0 = 0.f;
                        if (!(inx && (unsigned)(gyb+1)<(unsigned)H)) o1 = 0.f;
                        if (!(inx && (unsigned)(gyb+2)<(unsigned)H)) o2 = 0.f;
                        if (!(inx && (unsigned)(gyb+3)<(unsigned)H)) o3 = 0.f;
                    }
                    S[OFF_C + 2304 + (r4 + 0) * 48 + c] = o0;
                    S[OFF_C + 2304 + (r4 + 1) * 48 + c] = o1;
                    S[OFF_C + 2304 + (r4 + 2) * 48 + c] = o2;
                    S[OFF_C + 2304 + (r4 + 3) * 48 + c] = o3;
                }
            } else {
                int r = idx / 12, g4 = (idx - r * 12) * 4;
                #pragma unroll
                for (int arr = 0; arr < 2; ++arr) {
                    const float* p = S + OFF_B + arr * 2688 + r * 56 + g4;
                    float4 A = *(const float4*)p;
                    float4 Bv = *(const float4*)(p + 4);
                    float4 Cv = *(const float4*)(p + 8);
                    float t0=A.x,t1=A.y,t2=A.z,t3=A.w,t4=Bv.x,t5=Bv.y,t6=Bv.z,t7=Bv.w,t8=Cv.x,t9=Cv.y,t10=Cv.z,t11=Cv.w;
                    float4 o;
                    if (arr == 0) {
                        float cx = fmaxf(fmaxf(fmaxf(t3,t4),fmaxf(t5,t6)),fmaxf(t7,t8));
                        o.x = fmaxf(fmaxf(fmaxf(cx,t0),t1),t2);
                        o.y = fmaxf(fmaxf(fmaxf(cx,t1),t2),t9);
                        o.z = fmaxf(fmaxf(fmaxf(cx,t2),t9),t10);
                        o.w = fmaxf(fmaxf(fmaxf(cx,t9),t10),t11);
                    } else {
                        float cn = fminf(fminf(fminf(t3,t4),fminf(t5,t6)),fminf(t7,t8));
                        o.x = fminf(fminf(fminf(cn,t0),t1),t2);
                        o.y = fminf(fminf(fminf(cn,t1),t2),t9);
                        o.z = fminf(fminf(fminf(cn,t2),t9),t10);
                        o.w = fminf(fminf(fminf(cn,t9),t10),t11);
                    }
                    *(float4*)(S + OFF_C + arr * 2304 + r * 48 + g4) = o;
                }
            }
        } else {
            int k = idx - 576;    // 484 items -> go
            if (DIR == 0) {
                int rg = k / 44, c = k - rg * 44;
                int r4 = rg * 4;
                float t[8];
                #pragma unroll
                for (int q = 0; q < 8; ++q) t[q] = S[OFF_D + (r4 + q) * 44 + c];
                float s0 = t[0] + t[1] + t[2] + t[3] + t[4];
                float s1 = s0 - t[0] + t[5];
                float s2 = s1 - t[1] + t[6];
                float s3 = s2 - t[2] + t[7];
                float ss[4] = { s0, s1, s2, s3 };
                #pragma unroll
                for (int j = 0; j < 4; ++j) {
                    float v;
                    if (!BORDER) {
                        v = fabsf(ss[j] * 0.04f);
                    } else {
                        int gx = X0 - 6 + c, gy = Y0 - 6 + r4 + j;
                        if ((unsigned)gx < (unsigned)W && (unsigned)gy < (unsigned)H) {
                            float cntx = (float)(min(gx + 2, W - 1) - max(gx - 2, 0) + 1);
                            float cnty = (float)(min(gy + 2, H - 1) - max(gy - 2, 0) + 1);
                            v = fabsf(__fdividef(ss[j], cntx * cnty));
                        } else v = NANF;
                    }
                    S[OFF_GO + (r4 + j) * 44 + c] = v;
                }
            } else {
                int r = k / 11, c4 = (k - r * 11) * 4;
                float4 A = *(const float4*)(S + OFF_D + r * 48 + c4);
                float4 Bv = *(const float4*)(S + OFF_D + r * 48 + c4 + 4);
                float t0=A.x,t1=A.y,t2=A.z,t3=A.w,t4=Bv.x,t5=Bv.y,t6=Bv.z,t7=Bv.w;
                float s0 = t0 + t1 + t2 + t3 + t4;
                float s1 = s0 - t0 + t5;
                float s2 = s1 - t1 + t6;
                float s3 = s2 - t2 + t7;
                float ss[4] = { s0, s1, s2, s3 };
                float4 o;
                float* op = &o.x;
                #pragma unroll
                for (int j = 0; j < 4; ++j) {
                    float v;
                    if (!BORDER) {
                        v = fabsf(ss[j] * 0.04f);
                    } else {
                        int gx = X0 - 6 + c4 + j, gy = Y0 - 6 + r;
                        if ((unsigned)gx < (unsigned)W && (unsigned)gy < (unsigned)H) {
                            float cntx = (float)(min(gx + 2, W - 1) - max(gx - 2, 0) + 1);
                            float cnty = (float)(min(gy + 2, H - 1) - max(gy - 2, 0) + 1);
                            v = fabsf(__fdividef(ss[j], cntx * cnty));
                        } else v = NANF;
                    }
                    op[j] = v;
                }
                *(float4*)(S + OFF_GO + r * 44 + c4) = o;
            }
        }
    }
    __syncthreads();

    // ======== P4: h17 (48x32) + h7 (44x38) ========
    #pragma unroll
    for (int idx = tid; idx < 824; idx += NT) {
        if (idx < 384) {
            int r = idx / 8, g4 = (idx & 7) * 4;
            #pragma unroll
            for (int arr = 0; arr < 2; ++arr) {
                const float* p = S + OFF_C + arr * 2304 + r * 48 + g4;
                float t[20];
                #pragma unroll
                for (int q = 0; q < 5; ++q) {
                    float4 v = *(const float4*)(p + q * 4);
                    t[q*4] = v.x; t[q*4+1] = v.y; t[q*4+2] = v.z; t[q*4+3] = v.w;
                }
                float s0 = 0.f;
                #pragma unroll
                for (int q = 0; q < 17; ++q) s0 += t[q];
                float s1 = s0 - t[0] + t[17];
                float s2 = s1 - t[1] + t[18];
                float s3 = s2 - t[2] + t[19];
                *(float4*)(S + OFF_B + arr * 1536 + r * 32 + g4) = make_float4(s0, s1, s2, s3);
            }
        } else {
            int k = idx - 384;     // 440 items
            int r = k / 10, g = k - r * 10;
            if (g < 9) {
                int g4 = g * 4;
                const float* p = S + OFF_GO + r * 44 + g4;
                float4 A = *(const float4*)p;
                float4 Bv = *(const float4*)(p + 4);
                float4 Cv = *(const float4*)(p + 8);
                float t0=A.x,t1=A.y,t2=A.z,t3=A.w,t4=Bv.x,t5=Bv.y,t6=Bv.z,t7=Bv.w,t8=Cv.x,t9=Cv.y;
                float cx = fmaxf(fmaxf(t3,t4),fmaxf(t5,t6));
                float cn = fminf(fminf(t3,t4),fminf(t5,t6));
                float4 ox, on;
                ox.x = fmaxf(fmaxf(fmaxf(cx,t0),t1),t2);
                ox.y = fmaxf(fmaxf(fmaxf(cx,t1),t2),t7);
                ox.z = fmaxf(fmaxf(fmaxf(cx,t2),t7),t8);
                ox.w = fmaxf(fmaxf(fmaxf(cx,t7),t8),t9);
                on.x = fminf(fminf(fminf(cn,t0),t1),t2);
                on.y = fminf(fminf(fminf(cn,t1),t2),t7);
                on.z = fminf(fminf(fminf(cn,t2),t7),t8);
                on.w = fminf(fminf(fminf(cn,t7),t8),t9);
                *(float4*)(S + OFF_A + r * 40 + g4) = ox;
                *(float4*)(S + OFF_A + 1760 + r * 40 + g4) = on;
            } else {
                const float* p = S + OFF_GO + r * 44 + 36;
                float4 A = *(const float4*)p;
                float4 Bv = *(const float4*)(p + 4);
                float t0=A.x,t1=A.y,t2=A.z,t3=A.w,t4=Bv.x,t5=Bv.y,t6=Bv.z,t7=Bv.w;
                float c6x = fmaxf(fmaxf(t1,t2),fmaxf(fmaxf(t3,t4),fmaxf(t5,t6)));
                float c6n = fminf(fminf(t1,t2),fminf(fminf(t3,t4),fminf(t5,t6)));
                S[OFF_A + r * 40 + 36] = fmaxf(c6x, t0);
                S[OFF_A + r * 40 + 37] = fmaxf(c6x, t7);
                S[OFF_A + 1760 + r * 40 + 36] = fminf(c6n, t0);
                S[OFF_A + 1760 + r * 40 + 37] = fminf(c6n, t7);
            }
        }
    }
    __syncthreads();

    // ======== P5: v17 -> regs on tids 0-255  ||  m7 on tids 256-511 ========
    if (tid < 256) {
        int rg = tid >> 5, c = tid & 31;
        int r0 = rg * 4;
        float inv[4];
        if (!BORDER) {
            #pragma unroll
            for (int j = 0; j < 4; ++j) inv[j] = 1.f / 289.f;
        } else {
            int gx = X0 + c;
            float cntx = (float)(min(gx + 8, W - 1) - max(gx - 8, 0) + 1);
            #pragma unroll
            for (int j = 0; j < 4; ++j) {
                int gy = Y0 + r0 + j;
                float cnty = (float)(min(gy + 8, H - 1) - max(gy - 8, 0) + 1);
                inv[j] = __fdividef(1.f, cntx * cnty);
            }
        }
        {
            float t[20];
            #pragma unroll
            for (int q = 0; q < 20; ++q) t[q] = S[OFF_B + (r0 + q) * 32 + c];
            float s0 = 0.f;
            #pragma unroll
            for (int q = 0; q < 17; ++q) s0 += t[q];
            float s1 = s0 - t[0] + t[17];
            float s2 = s1 - t[1] + t[18];
            float s3 = s2 - t[2] + t[19];
            gmv[0] = s0 * inv[0]; gmv[1] = s1 * inv[1];
            gmv[2] = s2 * inv[2]; gmv[3] = s3 * inv[3];
        }
        {
            float t[20];
            #pragma unroll
            for (int q = 0; q < 20; ++q) t[q] = S[OFF_B + 1536 + (r0 + q) * 32 + c];
            float s0 = 0.f;
            #pragma unroll
            for (int q = 0; q < 17; ++q) s0 += t[q];
            float s1 = s0 - t[0] + t[17];
            float s2 = s1 - t[1] + t[18];
            float s3 = s2 - t[2] + t[19];
            gnv[0] = s0 * inv[0]; gnv[1] = s1 * inv[1];
            gnv[2] = s2 * inv[2]; gnv[3] = s3 * inv[3];
        }
    } else {
        #pragma unroll
        for (int k = tid - 256; k < 380; k += 256) {
            int rg = k / 38, c = k - rg * 38;
            int r0 = min(rg * 4, 34);
            #pragma unroll
            for (int arr = 0; arr < 2; ++arr) {
                float t[10];
                #pragma unroll
                for (int q = 0; q < 10; ++q) t[q] = S[OFF_A + arr * 1760 + (r0 + q) * 40 + c];
                float o0, o1, o2, o3;
                if (arr == 0) {
                    float cx = fmaxf(fmaxf(t[3],t[4]),fmaxf(t[5],t[6]));
                    o0 = fmaxf(fmaxf(fmaxf(cx,t[0]),t[1]),t[2]);
                    o1 = fmaxf(fmaxf(fmaxf(cx,t[1]),t[2]),t[7]);
                    o2 = fmaxf(fmaxf(fmaxf(cx,t[2]),t[7]),t[8]);
                    o3 = fmaxf(fmaxf(fmaxf(cx,t[7]),t[8]),t[9]);
                } else {
                    float cn = fminf(fminf(t[3],t[4]),fminf(t[5],t[6]));
                    o0 = fminf(fminf(fminf(cn,t[0]),t[1]),t[2]);
                    o1 = fminf(fminf(fminf(cn,t[1]),t[2]),t[7]);
                    o2 = fminf(fminf(fminf(cn,t[2]),t[7]),t[8]);
                    o3 = fminf(fminf(fminf(cn,t[7]),t[8]),t[9]);
                }
                if (BORDER) {
                    int gx = X0 - 3 + c;
                    bool inx = (unsigned)gx < (unsigned)W;
                    int gyb = Y0 - 3 + r0;
                    if (!(inx && (unsigned)(gyb+0)<(unsigned)H)) o0 = 0.f;
                    if (!(inx && (unsigned)(gyb+1)<(unsigned)H)) o1 = 0.f;
                    if (!(inx && (unsigned)(gyb+2)<(unsigned)H)) o2 = 0.f;
                    if (!(inx && (unsigned)(gyb+3)<(unsigned)H)) o3 = 0.f;
                }
                S[OFF_C + arr * 1520 + (r0 + 0) * 40 + c] = o0;
                S[OFF_C + arr * 1520 + (r0 + 1) * 40 + c] = o1;
                S[OFF_C + arr * 1520 + (r0 + 2) * 40 + c] = o2;
                S[OFF_C + arr * 1520 + (r0 + 3) * 40 + c] = o3;
            }
        }
    }
    __syncthreads();

    // ======== P6: h7s (38x32) ========
    #pragma unroll
    for (int idx = tid; idx < 304; idx += NT) {
        int r = idx / 8, g4 = (idx & 7) * 4;
        #pragma unroll
        for (int arr = 0; arr < 2; ++arr) {
            const float* p = S + OFF_C + arr * 1520 + r * 40 + g4;
            float4 A = *(const float4*)p;
            float4 Bv = *(const float4*)(p + 4);
            float4 Cv = *(const float4*)(p + 8);
            float t0=A.x,t1=A.y,t2=A.z,t3=A.w,t4=Bv.x,t5=Bv.y,t6=Bv.z,t7=Bv.w,t8=Cv.x,t9=Cv.y;
            float s0 = t0+t1+t2+t3+t4+t5+t6;
            float s1 = s0 - t0 + t7;
            float s2 = s1 - t1 + t8;
            float s3 = s2 - t2 + t9;
            *(float4*)(S + OFF_A + arr * 1216 + r * 32 + g4) = make_float4(s0, s1, s2, s3);
        }
    }
    __syncthreads();

    // ======== P7: final (32x32) ========
    if (tid < 256) {
        int rg = tid >> 5, c = tid & 31;
        int r0 = rg * 4;
        float sA[4], sD[4];
        {
            float t[10];
            #pragma unroll
            for (int q = 0; q < 10; ++q) t[q] = S[OFF_A + (r0 + q) * 32 + c];
            sA[0] = t[0]+t[1]+t[2]+t[3]+t[4]+t[5]+t[6];
            sA[1] = sA[0] - t[0] + t[7];
            sA[2] = sA[1] - t[1] + t[8];
            sA[3] = sA[2] - t[2] + t[9];
        }
        {
            float t[10];
            #pragma unroll
            for (int q = 0; q < 10; ++q) t[q] = S[OFF_A + 1216 + (r0 + q) * 32 + c];
            sD[0] = t[0]+t[1]+t[2]+t[3]+t[4]+t[5]+t[6];
            sD[1] = sD[0] - t[0] + t[7];
            sD[2] = sD[1] - t[1] + t[8];
            sD[3] = sD[2] - t[2] + t[9];
        }
        #pragma unroll
        for (int j = 0; j < 4; ++j) {
            float inv;
            if (!BORDER) {
                inv = 1.f / 49.f;
            } else {
                int gx = X0 + c, gy = Y0 + r0 + j;
                float cntx = (float)(min(gx + 3, W - 1) - max(gx - 3, 0) + 1);
                float cnty = (float)(min(gy + 3, H - 1) - max(gy - 3, 0) + 1);
                inv = __fdividef(1.f, cntx * cnty);
            }
            float pmax = sA[j] * inv, pmin = sD[j] * inv;
            float go = S[OFF_GO + (r0 + j + 6) * 44 + c + 6];
            float ga;
            if (BORDER) {
                ga = S[OFF_SGA + (r0 + j + 12) * 56 + c + 12];
            } else {
                int u = c + 12, rho = r0 + j + 12;
                float gc = S[OFF_GRAY + rho * 60 + u];
                float gn_ = (DIR == 0) ? S[OFF_GRAY + rho * 60 + u + 1]
                                       : S[OFF_GRAY + (rho + 1) * 60 + u];
                ga = fabsf(gc - gn_);
            }
            float gn = __fdividef(go - pmin, fabsf(pmax - pmin) + EPSF);
            float gn1 = __fdividef(ga - gnv[j], fabsf(gmv[j] - gnv[j]) + EPSF);
            float val = (gn + 0.01f) * gn1;
            if (mode == 0) {
                vsave[j] = val;
            } else {
                float rv = vsave[j];
                acc += (double)(rv * expf(-10.f * (rv + val)));
            }
        }
    }
    // End-of-pipe barrier needed only when the next pipe's P1 rewrites sga
    // (BORDER). Interior: next pipe's first writes (hm/vm -> B, hs5/vs5 -> D)
    // are disjoint from P7's reads (A, go, gray), and P2's end barrier orders
    // everything afterward.
    if (BORDER) __syncthreads();
}

template<bool BORDER>
__device__ __forceinline__ void run(float* S, int X0, int Y0, int b, int tid, double& acc,
                                    const float* __restrict__ img0,
                                    const float* __restrict__ img1)
{
    float vsx[4], vsy[4];
    #pragma unroll
    for (int img = 0; img < 2; ++img) {
        const float* __restrict__ ip = (img == 0 ? img0 : img1) + (size_t)b * 3 * NPIX;
        if (!BORDER) {
            #pragma unroll
            for (int idx = tid; idx < 870; idx += NT) {
                int r = idx / 15, c4 = (idx - r * 15) * 4;
                size_t off = (size_t)(Y0 - 12 + r) * W + (X0 - 12 + c4);
                float4 rv = *(const float4*)(ip + off);
                float4 gv = *(const float4*)(ip + NPIX + off);
                float4 bv = *(const float4*)(ip + 2 * NPIX + off);
                float4 o;
                o.x = 0.299f * rv.x + 0.587f * gv.x + 0.114f * bv.x;
                o.y = 0.299f * rv.y + 0.587f * gv.y + 0.114f * bv.y;
                o.z = 0.299f * rv.z + 0.587f * gv.z + 0.114f * bv.z;
                o.w = 0.299f * rv.w + 0.587f * gv.w + 0.114f * bv.w;
                *(float4*)(S + OFF_GRAY + r * 60 + c4) = o;
            }
        } else {
            for (int idx = tid; idx < 3364; idx += NT) {
                int r = idx / 58, c = idx - r * 58;
                int gy = Y0 - 12 + r, gx = X0 - 12 + c;
                float v = 0.f;
                if ((unsigned)gx < (unsigned)W && (unsigned)gy < (unsigned)H) {
                    size_t off = (size_t)gy * W + gx;
                    v = 0.299f * __ldg(ip + off)
                      + 0.587f * __ldg(ip + NPIX + off)
                      + 0.114f * __ldg(ip + 2 * NPIX + off);
                }
                S[OFF_GRAY + r * 60 + c] = v;
            }
        }
        __syncthreads();
        pipe<0, BORDER>(S, X0, Y0, tid, img, vsx, acc);
        pipe<1, BORDER>(S, X0, Y0, tid, img, vsy, acc);
        __syncthreads();   // protect gray tile before next img overwrites
    }
}

__global__ __launch_bounds__(NT, 2)
void k_mega(const float* __restrict__ img0, const float* __restrict__ img1) {
    extern __shared__ float S[];
    __shared__ double sred[NT / 32];

    const int b = blockIdx.z;
    const int X0 = blockIdx.x * 32, Y0 = blockIdx.y * 32;
    const int tid = threadIdx.x;

    double acc = 0.0;
    bool border = (blockIdx.x == 0) | (blockIdx.x == 15) | (blockIdx.y == 0) | (blockIdx.y == 15);
    if (border) run<true>(S, X0, Y0, b, tid, acc, img0, img1);
    else        run<false>(S, X0, Y0, b, tid, acc, img0, img1);

    int tx = tid & 31, ty = tid >> 5;
    #pragma unroll
    for (int off = 16; off; off >>= 1) acc += __shfl_down_sync(0xffffffffu, acc, off);
    if (tx == 0) sred[ty] = acc;
    __syncthreads();
    if (ty == 0 && tx < NT / 32) {
        double w = sred[tx];
        #pragma unroll
        for (int off = (NT / 64); off; off >>= 1) w += __shfl_down_sync(0xffffffffu, w, off);
        if (tx == 0) atomicAdd(&g_acc, w);
    }
}

// Reads the accumulator, writes the output, and resets for the next graph
// replay. First launch sees the zero-initialized static; every subsequent
// replay sees this reset. Deterministic across replays.
__global__ void k_out(float* __restrict__ out) {
    out[0] = (float)(g_acc / (double)NMAP);
    g_acc = 0.0;
}

extern "C" void kernel_launch(void* const* d_in, const int* in_sizes, int n_in,
                              void* d_out, int out_size) {
    const float* R_low = (const float*)d_in[0];
    const float* low = (const float*)d_in[1];
    float* out = (float*)d_out;

    cudaFuncSetAttribute(k_mega, cudaFuncAttributeMaxDynamicSharedMemorySize, SMEM_BYTES);

    dim3 grd(16, 16, 16);
    k_mega<<<grd, NT, SMEM_BYTES>>>(R_low, low);
    k_out<<<1, 1>>>(out);
}